// round 1
// baseline (speedup 1.0000x reference)
#include <cuda_runtime.h>
#include <math.h>

// ---------------------------------------------------------------------------
// Problem constants
// ---------------------------------------------------------------------------
#define BATCH 4
#define SEQ   2048
#define DMODEL 1024
#define NHEADS 16
#define DK    64
#define DFF   4096
#define MROWS (BATCH * SEQ)   // 8192

// ---------------------------------------------------------------------------
// Scratch (no cudaMalloc allowed)
// ---------------------------------------------------------------------------
__device__ float g_q  [MROWS * DMODEL];
__device__ float g_k  [MROWS * DMODEL];
__device__ float g_v  [MROWS * DMODEL];
__device__ float g_ctx[MROWS * DMODEL];
__device__ float g_t1 [MROWS * DMODEL];
__device__ float g_h  [MROWS * DMODEL];
__device__ float g_ff [MROWS * DFF];

// ---------------------------------------------------------------------------
// SGEMM: C[M,N] = A[M,K] @ B[K,N] + bias[N]  (optional ReLU)
// BM=BN=128, BK=16, 256 threads, 8x8 per-thread tile.
// All problem dims are multiples of the tile sizes -> no bounds checks.
// ---------------------------------------------------------------------------
__global__ __launch_bounds__(256) void sgemm_bias(
    int M, int N, int K,
    const float* __restrict__ A, const float* __restrict__ B,
    const float* __restrict__ bias, float* __restrict__ C, int relu)
{
    constexpr int BM = 128, BN = 128, BK = 16, TM = 8, TN = 8;
    __shared__ float As[BK][BM];   // A tile stored transposed
    __shared__ float Bs[BK][BN];

    const int tid  = threadIdx.x;
    const int cRow = blockIdx.y, cCol = blockIdx.x;

    const float* Ab = A + (size_t)cRow * BM * K;
    const float* Bb = B + cCol * BN;

    const int tCol = tid & 15;        // 0..15
    const int tRow = tid >> 4;        // 0..15
    const int aRow = tid >> 2;        // 0..63
    const int aCol = (tid & 3) << 2;  // 0,4,8,12
    const int bRow = tid >> 5;        // 0..7
    const int bCol = (tid & 31) << 2; // 0..124

    float acc[TM][TN];
    #pragma unroll
    for (int i = 0; i < TM; i++)
        #pragma unroll
        for (int j = 0; j < TN; j++) acc[i][j] = 0.f;

    for (int k0 = 0; k0 < K; k0 += BK) {
        #pragma unroll
        for (int r = 0; r < BM; r += 64) {
            float4 t = *(const float4*)(Ab + (size_t)(aRow + r) * K + k0 + aCol);
            As[aCol + 0][aRow + r] = t.x;
            As[aCol + 1][aRow + r] = t.y;
            As[aCol + 2][aRow + r] = t.z;
            As[aCol + 3][aRow + r] = t.w;
        }
        #pragma unroll
        for (int r = 0; r < BK; r += 8) {
            *(float4*)(&Bs[bRow + r][bCol]) =
                *(const float4*)(Bb + (size_t)(k0 + bRow + r) * N + bCol);
        }
        __syncthreads();

        #pragma unroll
        for (int k = 0; k < BK; k++) {
            float rm[TM], rn[TN];
            #pragma unroll
            for (int i = 0; i < TM; i++) rm[i] = As[k][tRow * TM + i];
            #pragma unroll
            for (int j = 0; j < TN; j++) rn[j] = Bs[k][tCol * TN + j];
            #pragma unroll
            for (int i = 0; i < TM; i++)
                #pragma unroll
                for (int j = 0; j < TN; j++)
                    acc[i][j] += rm[i] * rn[j];
        }
        __syncthreads();
    }

    #pragma unroll
    for (int i = 0; i < TM; i++) {
        size_t row = (size_t)cRow * BM + tRow * TM + i;
        #pragma unroll
        for (int j = 0; j < TN; j += 4) {
            int col = cCol * BN + tCol * TN + j;
            float4 v;
            v.x = acc[i][j + 0] + bias[col + 0];
            v.y = acc[i][j + 1] + bias[col + 1];
            v.z = acc[i][j + 2] + bias[col + 2];
            v.w = acc[i][j + 3] + bias[col + 3];
            if (relu) {
                v.x = fmaxf(v.x, 0.f); v.y = fmaxf(v.y, 0.f);
                v.z = fmaxf(v.z, 0.f); v.w = fmaxf(v.w, 0.f);
            }
            *(float4*)(C + row * N + col) = v;
        }
    }
}

// ---------------------------------------------------------------------------
// Flash attention, fp32. Block = one (batch, head, 64-row Q tile).
// 256 threads: thread (r, j) with r = tid/4 (q row), j = tid%4.
// Thread j owns score columns c = 4i+j and output dims d = 4i+j (i=0..15).
// Online softmax with running (m, l). Q row pre-scaled by 1/sqrt(64)=0.125.
// ---------------------------------------------------------------------------
__global__ __launch_bounds__(256) void attn_kernel(
    const float* __restrict__ Q, const float* __restrict__ K,
    const float* __restrict__ V, const int* __restrict__ mask,
    float* __restrict__ O)
{
    const int qt = blockIdx.x, h = blockIdx.y, b = blockIdx.z;
    const int tid = threadIdx.x;
    const int r = tid >> 2, j = tid & 3;

    __shared__ float Ks[64][65];   // pad -> conflict-free Ks[4i+j][d]
    __shared__ float Vs[64][64];   // uniform-c reads -> no pad needed

    const size_t headoff = (size_t)h * DK;
    const size_t qbase = ((size_t)b * SEQ + qt * 64) * DMODEL + headoff;

    // Stage the Q tile through Vs (coalesced), then copy own row to registers.
    #pragma unroll
    for (int it = 0; it < 4; it++) {
        int idx = tid + it * 256;
        int row = idx >> 4;
        int c4  = (idx & 15) << 2;
        *(float4*)&Vs[row][c4] =
            *(const float4*)(Q + qbase + (size_t)row * DMODEL + c4);
    }
    __syncthreads();
    float q[64];
    #pragma unroll
    for (int d = 0; d < 64; d++) q[d] = Vs[r][d] * 0.125f;
    __syncthreads();

    float m = -INFINITY, l = 0.f;
    float acc[16];
    #pragma unroll
    for (int i = 0; i < 16; i++) acc[i] = 0.f;

    const int grp = (tid & 31) & ~3;   // base lane of this row's 4-lane group

    for (int kt = 0; kt < 32; kt++) {
        const size_t kbase = ((size_t)b * SEQ + kt * 64) * DMODEL + headoff;
        #pragma unroll
        for (int it = 0; it < 4; it++) {
            int idx = tid + it * 256;
            int row = idx >> 4;
            int c4  = (idx & 15) << 2;
            float4 kv = *(const float4*)(K + kbase + (size_t)row * DMODEL + c4);
            Ks[row][c4 + 0] = kv.x; Ks[row][c4 + 1] = kv.y;
            Ks[row][c4 + 2] = kv.z; Ks[row][c4 + 3] = kv.w;
            *(float4*)&Vs[row][c4] =
                *(const float4*)(V + kbase + (size_t)row * DMODEL + c4);
        }
        __syncthreads();

        // Scores for this thread's 16 columns
        float s[16];
        #pragma unroll
        for (int i = 0; i < 16; i++) {
            int c = 4 * i + j;
            float a0 = 0.f;
            #pragma unroll
            for (int d = 0; d < 64; d++) a0 += q[d] * Ks[c][d];
            s[i] = a0;
        }
        // Mask (src_mask[b,0,0,key] == 0 -> -inf)
        const int* mrow = mask + (size_t)b * SEQ + kt * 64;
        #pragma unroll
        for (int i = 0; i < 16; i++)
            if (mrow[4 * i + j] == 0) s[i] = -INFINITY;

        // Row max across the 4-lane group
        float tmax = s[0];
        #pragma unroll
        for (int i = 1; i < 16; i++) tmax = fmaxf(tmax, s[i]);
        tmax = fmaxf(tmax, __shfl_xor_sync(0xffffffffu, tmax, 1));
        tmax = fmaxf(tmax, __shfl_xor_sync(0xffffffffu, tmax, 2));
        float mnew = fmaxf(m, tmax);
        float corr = __expf(fmaxf(m - mnew, -80.f));  // guard -inf - -inf

        float p[16];
        float ssum = 0.f;
        #pragma unroll
        for (int i = 0; i < 16; i++) {
            p[i] = __expf(s[i] - mnew);
            ssum += p[i];
        }
        ssum += __shfl_xor_sync(0xffffffffu, ssum, 1);
        ssum += __shfl_xor_sync(0xffffffffu, ssum, 2);
        l = l * corr + ssum;
        m = mnew;
        #pragma unroll
        for (int i = 0; i < 16; i++) acc[i] *= corr;

        // O += P @ V ; c is uniform per step -> Vs reads are broadcast, no conflicts
        #pragma unroll
        for (int jj = 0; jj < 4; jj++) {
            #pragma unroll
            for (int ii = 0; ii < 16; ii++) {
                int c = 4 * ii + jj;
                float pc = __shfl_sync(0xffffffffu, p[ii], grp + jj);
                #pragma unroll
                for (int i = 0; i < 16; i++)
                    acc[i] += pc * Vs[c][4 * i + j];
            }
        }
        __syncthreads();
    }

    float inv = 1.f / l;
    float* orow = O + qbase + (size_t)r * DMODEL;
    #pragma unroll
    for (int i = 0; i < 16; i++) orow[4 * i + j] = acc[i] * inv;
}

// ---------------------------------------------------------------------------
// out[row] = LayerNorm(a[row] + b[row]) * gamma + beta, one block per row.
// ---------------------------------------------------------------------------
__global__ __launch_bounds__(256) void add_ln_kernel(
    const float* __restrict__ a, const float* __restrict__ bsrc,
    const float* __restrict__ g, const float* __restrict__ be,
    float* __restrict__ out)
{
    const int row = blockIdx.x;
    const int tid = threadIdx.x;
    const float* pa = a + (size_t)row * DMODEL;
    const float* pb = bsrc + (size_t)row * DMODEL;

    float v[4];
    float sum = 0.f, sq = 0.f;
    #pragma unroll
    for (int i = 0; i < 4; i++) {
        int c = tid + i * 256;
        float x = pa[c] + pb[c];
        v[i] = x;
        sum += x;
        sq += x * x;
    }
    #pragma unroll
    for (int o = 16; o > 0; o >>= 1) {
        sum += __shfl_xor_sync(0xffffffffu, sum, o);
        sq  += __shfl_xor_sync(0xffffffffu, sq,  o);
    }
    __shared__ float ssum[8], ssq[8];
    if ((tid & 31) == 0) { ssum[tid >> 5] = sum; ssq[tid >> 5] = sq; }
    __syncthreads();
    if (tid < 32) {
        float s2 = (tid < 8) ? ssum[tid] : 0.f;
        float q2 = (tid < 8) ? ssq[tid] : 0.f;
        #pragma unroll
        for (int o = 4; o > 0; o >>= 1) {
            s2 += __shfl_xor_sync(0xffffffffu, s2, o);
            q2 += __shfl_xor_sync(0xffffffffu, q2, o);
        }
        if (tid == 0) { ssum[0] = s2; ssq[0] = q2; }
    }
    __syncthreads();
    const float mu   = ssum[0] * (1.f / DMODEL);
    const float var  = ssq[0] * (1.f / DMODEL) - mu * mu;
    const float rstd = rsqrtf(var + 1e-5f);

    float* po = out + (size_t)row * DMODEL;
    #pragma unroll
    for (int i = 0; i < 4; i++) {
        int c = tid + i * 256;
        po[c] = (v[i] - mu) * rstd * g[c] + be[c];
    }
}

// ---------------------------------------------------------------------------
// Launch
// ---------------------------------------------------------------------------
extern "C" void kernel_launch(void* const* d_in, const int* in_sizes, int n_in,
                              void* d_out, int out_size)
{
    (void)in_sizes; (void)n_in; (void)out_size;
    const float* x    = (const float*)d_in[0];
    const int*   mask = (const int*)  d_in[1];
    const float* w_q  = (const float*)d_in[2];
    const float* b_q  = (const float*)d_in[3];
    const float* w_k  = (const float*)d_in[4];
    const float* b_k  = (const float*)d_in[5];
    const float* w_v  = (const float*)d_in[6];
    const float* b_v  = (const float*)d_in[7];
    const float* w_o  = (const float*)d_in[8];
    const float* b_o  = (const float*)d_in[9];
    const float* w1   = (const float*)d_in[10];
    const float* b1   = (const float*)d_in[11];
    const float* w2   = (const float*)d_in[12];
    const float* b2   = (const float*)d_in[13];
    const float* g1   = (const float*)d_in[14];
    const float* be1  = (const float*)d_in[15];
    const float* g2   = (const float*)d_in[16];
    const float* be2  = (const float*)d_in[17];

    float *q, *k, *v, *ctx, *t1, *h, *ff;
    cudaGetSymbolAddress((void**)&q,   g_q);
    cudaGetSymbolAddress((void**)&k,   g_k);
    cudaGetSymbolAddress((void**)&v,   g_v);
    cudaGetSymbolAddress((void**)&ctx, g_ctx);
    cudaGetSymbolAddress((void**)&t1,  g_t1);
    cudaGetSymbolAddress((void**)&h,   g_h);
    cudaGetSymbolAddress((void**)&ff,  g_ff);

    dim3 blk(256);
    dim3 gProj(DMODEL / 128, MROWS / 128);   // (8, 64)
    dim3 gFF1(DFF / 128, MROWS / 128);       // (32, 64)
    dim3 gAtt(SEQ / 64, NHEADS, BATCH);      // (32, 16, 4)

    sgemm_bias<<<gProj, blk>>>(MROWS, DMODEL, DMODEL, x, w_q, b_q, q, 0);
    sgemm_bias<<<gProj, blk>>>(MROWS, DMODEL, DMODEL, x, w_k, b_k, k, 0);
    sgemm_bias<<<gProj, blk>>>(MROWS, DMODEL, DMODEL, x, w_v, b_v, v, 0);

    attn_kernel<<<gAtt, blk>>>(q, k, v, mask, ctx);

    sgemm_bias<<<gProj, blk>>>(MROWS, DMODEL, DMODEL, ctx, w_o, b_o, t1, 0);
    add_ln_kernel<<<MROWS, 256>>>(x, t1, g1, be1, h);

    sgemm_bias<<<gFF1, blk>>>(MROWS, DFF, DMODEL, h, w1, b1, ff, 1);
    sgemm_bias<<<gProj, blk>>>(MROWS, DMODEL, DFF, ff, w2, b2, t1, 0);
    add_ln_kernel<<<MROWS, 256>>>(h, t1, g2, be2, (float*)d_out);
}

// round 3
// speedup vs baseline: 2.6656x; 2.6656x over previous
#include <cuda_runtime.h>
#include <math.h>

// ---------------------------------------------------------------------------
// Problem constants
// ---------------------------------------------------------------------------
#define BATCH 4
#define SEQ   2048
#define DMODEL 1024
#define NHEADS 16
#define DK    64
#define DFF   4096
#define MROWS (BATCH * SEQ)   // 8192

// ---------------------------------------------------------------------------
// Scratch (no cudaMalloc allowed)
// ---------------------------------------------------------------------------
__device__ float g_q  [MROWS * DMODEL];
__device__ float g_k  [MROWS * DMODEL];
__device__ float g_v  [MROWS * DMODEL];
__device__ float g_ctx[MROWS * DMODEL];
__device__ float g_t1 [MROWS * DMODEL];
__device__ float g_h  [MROWS * DMODEL];
__device__ float g_ff [MROWS * DFF];

// ---------------------------------------------------------------------------
// Helpers
// ---------------------------------------------------------------------------
__device__ __forceinline__ unsigned cvt_tf32(float x) {
    unsigned r;
    asm("cvt.rna.tf32.f32 %0, %1;" : "=r"(r) : "f"(x));
    return r;
}

__device__ __forceinline__ void mma_tf32(float* c, const unsigned* a, const unsigned* b) {
    asm volatile(
        "mma.sync.aligned.m16n8k8.row.col.f32.tf32.tf32.f32 "
        "{%0,%1,%2,%3}, {%4,%5,%6,%7}, {%8,%9}, {%0,%1,%2,%3};"
        : "+f"(c[0]), "+f"(c[1]), "+f"(c[2]), "+f"(c[3])
        : "r"(a[0]), "r"(a[1]), "r"(a[2]), "r"(a[3]), "r"(b[0]), "r"(b[1]));
}

// Packed fp32x2 FMA: d += a * b (elementwise on 2 floats)
__device__ __forceinline__ void ffma2(float2& d, float2 a, float2 b) {
    asm("fma.rn.f32x2 %0, %1, %2, %0;"
        : "+l"(*reinterpret_cast<unsigned long long*>(&d))
        : "l"(*reinterpret_cast<unsigned long long*>(&a)),
          "l"(*reinterpret_cast<unsigned long long*>(&b)));
}

// ---------------------------------------------------------------------------
// TF32 tensor-core GEMM: C[M,N] = A[M,K] @ B[K,N] + bias[N] (optional ReLU)
// BM=BN=128, BK=32, 256 threads = 8 warps (2x4), warp tile 64x32.
// ---------------------------------------------------------------------------
#define AS_STRIDE 36
#define BS_STRIDE 132

__global__ __launch_bounds__(256) void gemm_tf32(
    int M, int N, int K,
    const float* __restrict__ A, const float* __restrict__ B,
    const float* __restrict__ bias, float* __restrict__ C, int relu)
{
    __shared__ unsigned As[128 * AS_STRIDE];
    __shared__ unsigned Bs[32 * BS_STRIDE];

    const int tid  = threadIdx.x;
    const int lane = tid & 31;
    const int warp = tid >> 5;
    const int wm = (warp >> 2) * 64;   // warp row offset within block (0 / 64)
    const int wn = (warp & 3) * 32;    // warp col offset (0/32/64/96)
    const int g = lane >> 2;           // 0..7
    const int t = lane & 3;            // 0..3
    const int cRow = blockIdx.y, cCol = blockIdx.x;

    const int aRow = tid >> 3;         // 0..31
    const int aCol = (tid & 7) * 4;    // 0..28
    const int bRow = tid >> 5;         // 0..7
    const int bCol = (tid & 31) * 4;   // 0..124

    const float* Ag = A + (size_t)(cRow * 128) * K;
    const float* Bg = B + cCol * 128;

    float acc[4][4][4];
    #pragma unroll
    for (int i = 0; i < 4; i++)
        #pragma unroll
        for (int j = 0; j < 4; j++)
            #pragma unroll
            for (int e = 0; e < 4; e++) acc[i][j][e] = 0.f;

    for (int k0 = 0; k0 < K; k0 += 32) {
        // Load + convert A tile (128x32)
        #pragma unroll
        for (int r = 0; r < 4; r++) {
            float4 v = *(const float4*)(Ag + (size_t)(aRow + r * 32) * K + k0 + aCol);
            uint4 u = make_uint4(cvt_tf32(v.x), cvt_tf32(v.y), cvt_tf32(v.z), cvt_tf32(v.w));
            *(uint4*)&As[(aRow + r * 32) * AS_STRIDE + aCol] = u;
        }
        // Load + convert B tile (32x128)
        #pragma unroll
        for (int r = 0; r < 4; r++) {
            float4 v = *(const float4*)(Bg + (size_t)(k0 + bRow + r * 8) * N + bCol);
            uint4 u = make_uint4(cvt_tf32(v.x), cvt_tf32(v.y), cvt_tf32(v.z), cvt_tf32(v.w));
            *(uint4*)&Bs[(bRow + r * 8) * BS_STRIDE + bCol] = u;
        }
        __syncthreads();

        #pragma unroll
        for (int k8 = 0; k8 < 4; k8++) {
            const int kb = k8 * 8;
            unsigned af[4][4], bf[4][2];
            #pragma unroll
            for (int tm = 0; tm < 4; tm++) {
                int r0 = (wm + tm * 16 + g) * AS_STRIDE;
                af[tm][0] = As[r0 + kb + t];
                af[tm][1] = As[r0 + 8 * AS_STRIDE + kb + t];
                af[tm][2] = As[r0 + kb + 4 + t];
                af[tm][3] = As[r0 + 8 * AS_STRIDE + kb + 4 + t];
            }
            #pragma unroll
            for (int tn = 0; tn < 4; tn++) {
                bf[tn][0] = Bs[(kb + t) * BS_STRIDE + wn + tn * 8 + g];
                bf[tn][1] = Bs[(kb + 4 + t) * BS_STRIDE + wn + tn * 8 + g];
            }
            #pragma unroll
            for (int tm = 0; tm < 4; tm++)
                #pragma unroll
                for (int tn = 0; tn < 4; tn++)
                    mma_tf32(acc[tm][tn], af[tm], bf[tn]);
        }
        __syncthreads();
    }

    // Epilogue: bias (+ optional ReLU)
    #pragma unroll
    for (int tm = 0; tm < 4; tm++) {
        #pragma unroll
        for (int tn = 0; tn < 4; tn++) {
            int row = cRow * 128 + wm + tm * 16 + g;
            int col = cCol * 128 + wn + tn * 8 + 2 * t;
            float2 bb = *(const float2*)(bias + col);
            float2 v0 = make_float2(acc[tm][tn][0] + bb.x, acc[tm][tn][1] + bb.y);
            float2 v1 = make_float2(acc[tm][tn][2] + bb.x, acc[tm][tn][3] + bb.y);
            if (relu) {
                v0.x = fmaxf(v0.x, 0.f); v0.y = fmaxf(v0.y, 0.f);
                v1.x = fmaxf(v1.x, 0.f); v1.y = fmaxf(v1.y, 0.f);
            }
            *(float2*)(C + (size_t)row * N + col) = v0;
            *(float2*)(C + (size_t)(row + 8) * N + col) = v1;
        }
    }
}

// ---------------------------------------------------------------------------
// Flash attention, fp32 with packed f32x2 FMAs.
// Block = one (batch, head, 128-row Q tile); 256 threads.
// Thread (ty=tid/16, tx=tid%16) owns q rows ty*8..+7 and score cols tx*4..+3
// (and output dims tx*4..+3). K stored transposed in smem (stride 66).
// P kept in registers; redistributed for PV via warp shuffles (c uniform).
// ---------------------------------------------------------------------------
#define KT_STRIDE 66

__global__ __launch_bounds__(256, 2) void attn2(
    const float* __restrict__ Q, const float* __restrict__ K,
    const float* __restrict__ V, const int* __restrict__ mask,
    float* __restrict__ O)
{
    extern __shared__ float smem[];
    float* Qs  = smem;                 // 128*64
    float* KsT = Qs + 128 * 64;        // 64*66
    float* Vs  = KsT + 64 * KT_STRIDE; // 64*64

    const int qt = blockIdx.x, h = blockIdx.y, b = blockIdx.z;
    const int tid = threadIdx.x;
    const int tx = tid & 15, ty = tid >> 4, lane = tid & 31;
    const size_t hoff = (size_t)h * DK;
    const size_t qrow0 = (size_t)b * SEQ + qt * 128;

    // Load Q tile (scaled by 1/sqrt(64))
    #pragma unroll
    for (int it = 0; it < 8; it++) {
        int idx = tid + it * 256;
        int r = idx >> 4;
        int c4 = (idx & 15) << 2;
        float4 v = *(const float4*)(Q + (qrow0 + r) * DMODEL + hoff + c4);
        v.x *= 0.125f; v.y *= 0.125f; v.z *= 0.125f; v.w *= 0.125f;
        *(float4*)&Qs[r * 64 + c4] = v;
    }

    float m[8], l[8];
    float2 o2[8][2];
    #pragma unroll
    for (int i = 0; i < 8; i++) {
        m[i] = -INFINITY; l[i] = 0.f;
        o2[i][0] = make_float2(0.f, 0.f);
        o2[i][1] = make_float2(0.f, 0.f);
    }

    for (int kt = 0; kt < 32; kt++) {
        __syncthreads();   // previous tile fully consumed (also covers Qs store)

        // Load K tile transposed: KsT[d][c]
        {
            const int c = tid >> 2, t4 = tid & 3;
            const float* kg = K + ((size_t)b * SEQ + kt * 64 + c) * DMODEL + hoff + t4 * 16;
            #pragma unroll
            for (int q4 = 0; q4 < 4; q4++) {
                float4 v = *(const float4*)(kg + q4 * 4);
                int d = t4 * 16 + q4 * 4;
                KsT[(d + 0) * KT_STRIDE + c] = v.x;
                KsT[(d + 1) * KT_STRIDE + c] = v.y;
                KsT[(d + 2) * KT_STRIDE + c] = v.z;
                KsT[(d + 3) * KT_STRIDE + c] = v.w;
            }
        }
        // Load V tile (natural layout)
        #pragma unroll
        for (int it = 0; it < 4; it++) {
            int idx = tid + it * 256;
            int r = idx >> 4;
            int c4 = (idx & 15) << 2;
            *(float4*)&Vs[r * 64 + c4] =
                *(const float4*)(V + ((size_t)b * SEQ + kt * 64 + r) * DMODEL + hoff + c4);
        }
        __syncthreads();

        // ---- QK^T: s[8 rows][4 cols] with f32x2 ----
        float2 s2[8][2];
        #pragma unroll
        for (int i = 0; i < 8; i++) {
            s2[i][0] = make_float2(0.f, 0.f);
            s2[i][1] = make_float2(0.f, 0.f);
        }
        #pragma unroll
        for (int d0 = 0; d0 < 64; d0 += 4) {
            float2 k2[4][2];
            #pragma unroll
            for (int dd = 0; dd < 4; dd++) {
                k2[dd][0] = *(float2*)&KsT[(d0 + dd) * KT_STRIDE + tx * 4];
                k2[dd][1] = *(float2*)&KsT[(d0 + dd) * KT_STRIDE + tx * 4 + 2];
            }
            #pragma unroll
            for (int i = 0; i < 8; i++) {
                float4 qv = *(const float4*)&Qs[(ty * 8 + i) * 64 + d0];
                float2 q;
                q = make_float2(qv.x, qv.x); ffma2(s2[i][0], q, k2[0][0]); ffma2(s2[i][1], q, k2[0][1]);
                q = make_float2(qv.y, qv.y); ffma2(s2[i][0], q, k2[1][0]); ffma2(s2[i][1], q, k2[1][1]);
                q = make_float2(qv.z, qv.z); ffma2(s2[i][0], q, k2[2][0]); ffma2(s2[i][1], q, k2[2][1]);
                q = make_float2(qv.w, qv.w); ffma2(s2[i][0], q, k2[3][0]); ffma2(s2[i][1], q, k2[3][1]);
            }
        }

        // ---- Mask (src_mask[b,0,0,key]==0 -> -inf) ----
        {
            int4 mv = *(const int4*)(mask + (size_t)b * SEQ + kt * 64 + tx * 4);
            float f0 = (mv.x == 0) ? -INFINITY : 0.f;
            float f1 = (mv.y == 0) ? -INFINITY : 0.f;
            float f2 = (mv.z == 0) ? -INFINITY : 0.f;
            float f3 = (mv.w == 0) ? -INFINITY : 0.f;
            #pragma unroll
            for (int i = 0; i < 8; i++) {
                s2[i][0].x += f0;
                s2[i][0].y += f1;
                s2[i][1].x += f2;
                s2[i][1].y += f3;
            }
        }

        // ---- Online softmax per row (16-lane reductions) ----
        #pragma unroll
        for (int i = 0; i < 8; i++) {
            float mx = fmaxf(fmaxf(s2[i][0].x, s2[i][0].y), fmaxf(s2[i][1].x, s2[i][1].y));
            mx = fmaxf(mx, __shfl_xor_sync(0xffffffffu, mx, 1));
            mx = fmaxf(mx, __shfl_xor_sync(0xffffffffu, mx, 2));
            mx = fmaxf(mx, __shfl_xor_sync(0xffffffffu, mx, 4));
            mx = fmaxf(mx, __shfl_xor_sync(0xffffffffu, mx, 8));
            float mn = fmaxf(m[i], mx);
            float corr = __expf(m[i] - mn);   // m=-inf, mn finite -> 0
            s2[i][0].x = __expf(s2[i][0].x - mn);
            s2[i][0].y = __expf(s2[i][0].y - mn);
            s2[i][1].x = __expf(s2[i][1].x - mn);
            s2[i][1].y = __expf(s2[i][1].y - mn);
            float rs = s2[i][0].x + s2[i][0].y + s2[i][1].x + s2[i][1].y;
            rs += __shfl_xor_sync(0xffffffffu, rs, 1);
            rs += __shfl_xor_sync(0xffffffffu, rs, 2);
            rs += __shfl_xor_sync(0xffffffffu, rs, 4);
            rs += __shfl_xor_sync(0xffffffffu, rs, 8);
            l[i] = l[i] * corr + rs;
            m[i] = mn;
            o2[i][0].x *= corr; o2[i][0].y *= corr;
            o2[i][1].x *= corr; o2[i][1].y *= corr;
        }

        // ---- PV: O += P @ V  (P redistributed via shuffles; c uniform) ----
        #pragma unroll
        for (int u2 = 0; u2 < 2; u2++) {
            #pragma unroll
            for (int cm = 0; cm < 2; cm++) {
                #pragma unroll
                for (int tc = 0; tc < 16; tc++) {
                    const int c = tc * 4 + u2 * 2 + cm;
                    const int src = (lane & 16) | tc;
                    float2 v0 = *(float2*)&Vs[c * 64 + tx * 4];
                    float2 v1 = *(float2*)&Vs[c * 64 + tx * 4 + 2];
                    #pragma unroll
                    for (int i = 0; i < 8; i++) {
                        float pv = cm ? s2[i][u2].y : s2[i][u2].x;
                        float pc = __shfl_sync(0xffffffffu, pv, src);
                        float2 p2 = make_float2(pc, pc);
                        ffma2(o2[i][0], p2, v0);
                        ffma2(o2[i][1], p2, v1);
                    }
                }
            }
        }
    }

    // Write output
    #pragma unroll
    for (int i = 0; i < 8; i++) {
        float inv = 1.f / l[i];
        float4 ov = make_float4(o2[i][0].x * inv, o2[i][0].y * inv,
                                o2[i][1].x * inv, o2[i][1].y * inv);
        *(float4*)(O + (qrow0 + ty * 8 + i) * DMODEL + hoff + tx * 4) = ov;
    }
}

// ---------------------------------------------------------------------------
// out[row] = LayerNorm(a[row] + b[row]) * gamma + beta, one block per row.
// ---------------------------------------------------------------------------
__global__ __launch_bounds__(256) void add_ln_kernel(
    const float* __restrict__ a, const float* __restrict__ bsrc,
    const float* __restrict__ g, const float* __restrict__ be,
    float* __restrict__ out)
{
    const int row = blockIdx.x;
    const int tid = threadIdx.x;
    const float* pa = a + (size_t)row * DMODEL;
    const float* pb = bsrc + (size_t)row * DMODEL;

    float v[4];
    float sum = 0.f, sq = 0.f;
    #pragma unroll
    for (int i = 0; i < 4; i++) {
        int c = tid + i * 256;
        float x = pa[c] + pb[c];
        v[i] = x;
        sum += x;
        sq += x * x;
    }
    #pragma unroll
    for (int o = 16; o > 0; o >>= 1) {
        sum += __shfl_xor_sync(0xffffffffu, sum, o);
        sq  += __shfl_xor_sync(0xffffffffu, sq,  o);
    }
    __shared__ float ssum[8], ssq[8];
    if ((tid & 31) == 0) { ssum[tid >> 5] = sum; ssq[tid >> 5] = sq; }
    __syncthreads();
    if (tid < 32) {
        float s2 = (tid < 8) ? ssum[tid] : 0.f;
        float q2 = (tid < 8) ? ssq[tid] : 0.f;
        #pragma unroll
        for (int o = 4; o > 0; o >>= 1) {
            s2 += __shfl_xor_sync(0xffffffffu, s2, o);
            q2 += __shfl_xor_sync(0xffffffffu, q2, o);
        }
        if (tid == 0) { ssum[0] = s2; ssq[0] = q2; }
    }
    __syncthreads();
    const float mu   = ssum[0] * (1.f / DMODEL);
    const float var  = ssq[0] * (1.f / DMODEL) - mu * mu;
    const float rstd = rsqrtf(var + 1e-5f);

    float* po = out + (size_t)row * DMODEL;
    #pragma unroll
    for (int i = 0; i < 4; i++) {
        int c = tid + i * 256;
        po[c] = (v[i] - mu) * rstd * g[c] + be[c];
    }
}

// ---------------------------------------------------------------------------
// Launch
// ---------------------------------------------------------------------------
extern "C" void kernel_launch(void* const* d_in, const int* in_sizes, int n_in,
                              void* d_out, int out_size)
{
    (void)in_sizes; (void)n_in; (void)out_size;
    const float* x    = (const float*)d_in[0];
    const int*   mask = (const int*)  d_in[1];
    const float* w_q  = (const float*)d_in[2];
    const float* b_q  = (const float*)d_in[3];
    const float* w_k  = (const float*)d_in[4];
    const float* b_k  = (const float*)d_in[5];
    const float* w_v  = (const float*)d_in[6];
    const float* b_v  = (const float*)d_in[7];
    const float* w_o  = (const float*)d_in[8];
    const float* b_o  = (const float*)d_in[9];
    const float* w1   = (const float*)d_in[10];
    const float* b1   = (const float*)d_in[11];
    const float* w2   = (const float*)d_in[12];
    const float* b2   = (const float*)d_in[13];
    const float* g1   = (const float*)d_in[14];
    const float* be1  = (const float*)d_in[15];
    const float* g2   = (const float*)d_in[16];
    const float* be2  = (const float*)d_in[17];

    float *q, *k, *v, *ctx, *t1, *h, *ff;
    cudaGetSymbolAddress((void**)&q,   g_q);
    cudaGetSymbolAddress((void**)&k,   g_k);
    cudaGetSymbolAddress((void**)&v,   g_v);
    cudaGetSymbolAddress((void**)&ctx, g_ctx);
    cudaGetSymbolAddress((void**)&t1,  g_t1);
    cudaGetSymbolAddress((void**)&h,   g_h);
    cudaGetSymbolAddress((void**)&ff,  g_ff);

    const int attn_smem = (128 * 64 + 64 * KT_STRIDE + 64 * 64) * 4;  // 66048 B
    cudaFuncSetAttribute(attn2, cudaFuncAttributeMaxDynamicSharedMemorySize, attn_smem);

    dim3 blk(256);
    dim3 gProj(DMODEL / 128, MROWS / 128);   // (8, 64)
    dim3 gFF1(DFF / 128, MROWS / 128);       // (32, 64)
    dim3 gAtt(SEQ / 128, NHEADS, BATCH);     // (16, 16, 4)

    gemm_tf32<<<gProj, blk>>>(MROWS, DMODEL, DMODEL, x, w_q, b_q, q, 0);
    gemm_tf32<<<gProj, blk>>>(MROWS, DMODEL, DMODEL, x, w_k, b_k, k, 0);
    gemm_tf32<<<gProj, blk>>>(MROWS, DMODEL, DMODEL, x, w_v, b_v, v, 0);

    attn2<<<gAtt, blk, attn_smem>>>(q, k, v, mask, ctx);

    gemm_tf32<<<gProj, blk>>>(MROWS, DMODEL, DMODEL, ctx, w_o, b_o, t1, 0);
    add_ln_kernel<<<MROWS, 256>>>(x, t1, g1, be1, h);

    gemm_tf32<<<gFF1, blk>>>(MROWS, DFF, DMODEL, h, w1, b1, ff, 1);
    gemm_tf32<<<gProj, blk>>>(MROWS, DMODEL, DFF, ff, w2, b2, t1, 0);
    add_ln_kernel<<<MROWS, 256>>>(h, t1, g2, be2, (float*)d_out);
}

// round 4
// speedup vs baseline: 2.7482x; 1.0310x over previous
#include <cuda_runtime.h>
#include <math.h>

// ---------------------------------------------------------------------------
// Problem constants
// ---------------------------------------------------------------------------
#define BATCH 4
#define SEQ   2048
#define DMODEL 1024
#define NHEADS 16
#define DK    64
#define DFF   4096
#define MROWS (BATCH * SEQ)   // 8192

// ---------------------------------------------------------------------------
// Scratch (no cudaMalloc allowed)
// ---------------------------------------------------------------------------
__device__ float g_q  [MROWS * DMODEL];
__device__ float g_k  [MROWS * DMODEL];
__device__ float g_v  [MROWS * DMODEL];
__device__ float g_ctx[MROWS * DMODEL];
__device__ float g_t1 [MROWS * DMODEL];
__device__ float g_h  [MROWS * DMODEL];
__device__ float g_ff [MROWS * DFF];

// ---------------------------------------------------------------------------
// Helpers
// ---------------------------------------------------------------------------
__device__ __forceinline__ unsigned cvt_tf32(float x) {
    unsigned r;
    asm("cvt.rna.tf32.f32 %0, %1;" : "=r"(r) : "f"(x));
    return r;
}

__device__ __forceinline__ void mma_tf32(float* c, const unsigned* a, const unsigned* b) {
    asm volatile(
        "mma.sync.aligned.m16n8k8.row.col.f32.tf32.tf32.f32 "
        "{%0,%1,%2,%3}, {%4,%5,%6,%7}, {%8,%9}, {%0,%1,%2,%3};"
        : "+f"(c[0]), "+f"(c[1]), "+f"(c[2]), "+f"(c[3])
        : "r"(a[0]), "r"(a[1]), "r"(a[2]), "r"(a[3]), "r"(b[0]), "r"(b[1]));
}

// Packed fp32x2 FMA: d += a * b (elementwise on 2 floats)
__device__ __forceinline__ void ffma2(float2& d, float2 a, float2 b) {
    asm("fma.rn.f32x2 %0, %1, %2, %0;"
        : "+l"(*reinterpret_cast<unsigned long long*>(&d))
        : "l"(*reinterpret_cast<unsigned long long*>(&a)),
          "l"(*reinterpret_cast<unsigned long long*>(&b)));
}

// ---------------------------------------------------------------------------
// TF32 tensor-core GEMM: C[M,N] = A[M,K] @ B[K,N] + bias[N] (optional ReLU)
// BM=BN=128, BK=32, 256 threads = 8 warps (2x4), warp tile 64x32.
// ---------------------------------------------------------------------------
#define AS_STRIDE 36
#define BS_STRIDE 132

__global__ __launch_bounds__(256) void gemm_tf32(
    int M, int N, int K,
    const float* __restrict__ A, const float* __restrict__ B,
    const float* __restrict__ bias, float* __restrict__ C, int relu)
{
    __shared__ unsigned As[128 * AS_STRIDE];
    __shared__ unsigned Bs[32 * BS_STRIDE];

    const int tid  = threadIdx.x;
    const int lane = tid & 31;
    const int warp = tid >> 5;
    const int wm = (warp >> 2) * 64;   // warp row offset within block (0 / 64)
    const int wn = (warp & 3) * 32;    // warp col offset (0/32/64/96)
    const int g = lane >> 2;           // 0..7
    const int t = lane & 3;            // 0..3
    const int cRow = blockIdx.y, cCol = blockIdx.x;

    const int aRow = tid >> 3;         // 0..31
    const int aCol = (tid & 7) * 4;    // 0..28
    const int bRow = tid >> 5;         // 0..7
    const int bCol = (tid & 31) * 4;   // 0..124

    const float* Ag = A + (size_t)(cRow * 128) * K;
    const float* Bg = B + cCol * 128;

    float acc[4][4][4];
    #pragma unroll
    for (int i = 0; i < 4; i++)
        #pragma unroll
        for (int j = 0; j < 4; j++)
            #pragma unroll
            for (int e = 0; e < 4; e++) acc[i][j][e] = 0.f;

    for (int k0 = 0; k0 < K; k0 += 32) {
        // Load + convert A tile (128x32)
        #pragma unroll
        for (int r = 0; r < 4; r++) {
            float4 v = *(const float4*)(Ag + (size_t)(aRow + r * 32) * K + k0 + aCol);
            uint4 u = make_uint4(cvt_tf32(v.x), cvt_tf32(v.y), cvt_tf32(v.z), cvt_tf32(v.w));
            *(uint4*)&As[(aRow + r * 32) * AS_STRIDE + aCol] = u;
        }
        // Load + convert B tile (32x128)
        #pragma unroll
        for (int r = 0; r < 4; r++) {
            float4 v = *(const float4*)(Bg + (size_t)(k0 + bRow + r * 8) * N + bCol);
            uint4 u = make_uint4(cvt_tf32(v.x), cvt_tf32(v.y), cvt_tf32(v.z), cvt_tf32(v.w));
            *(uint4*)&Bs[(bRow + r * 8) * BS_STRIDE + bCol] = u;
        }
        __syncthreads();

        #pragma unroll
        for (int k8 = 0; k8 < 4; k8++) {
            const int kb = k8 * 8;
            unsigned af[4][4], bf[4][2];
            #pragma unroll
            for (int tm = 0; tm < 4; tm++) {
                int r0 = (wm + tm * 16 + g) * AS_STRIDE;
                af[tm][0] = As[r0 + kb + t];
                af[tm][1] = As[r0 + 8 * AS_STRIDE + kb + t];
                af[tm][2] = As[r0 + kb + 4 + t];
                af[tm][3] = As[r0 + 8 * AS_STRIDE + kb + 4 + t];
            }
            #pragma unroll
            for (int tn = 0; tn < 4; tn++) {
                bf[tn][0] = Bs[(kb + t) * BS_STRIDE + wn + tn * 8 + g];
                bf[tn][1] = Bs[(kb + 4 + t) * BS_STRIDE + wn + tn * 8 + g];
            }
            #pragma unroll
            for (int tm = 0; tm < 4; tm++)
                #pragma unroll
                for (int tn = 0; tn < 4; tn++)
                    mma_tf32(acc[tm][tn], af[tm], bf[tn]);
        }
        __syncthreads();
    }

    // Epilogue: bias (+ optional ReLU)
    #pragma unroll
    for (int tm = 0; tm < 4; tm++) {
        #pragma unroll
        for (int tn = 0; tn < 4; tn++) {
            int row = cRow * 128 + wm + tm * 16 + g;
            int col = cCol * 128 + wn + tn * 8 + 2 * t;
            float2 bb = *(const float2*)(bias + col);
            float2 v0 = make_float2(acc[tm][tn][0] + bb.x, acc[tm][tn][1] + bb.y);
            float2 v1 = make_float2(acc[tm][tn][2] + bb.x, acc[tm][tn][3] + bb.y);
            if (relu) {
                v0.x = fmaxf(v0.x, 0.f); v0.y = fmaxf(v0.y, 0.f);
                v1.x = fmaxf(v1.x, 0.f); v1.y = fmaxf(v1.y, 0.f);
            }
            *(float2*)(C + (size_t)row * N + col) = v0;
            *(float2*)(C + (size_t)(row + 8) * N + col) = v1;
        }
    }
}

// ---------------------------------------------------------------------------
// Flash attention, fp32 with packed f32x2 FMAs.
// Block = one (batch, head, 128-row Q tile); 256 threads.
// Thread (ty=tid/16, tx=tid%16) owns q rows ty*8..+7 and score cols tx*4..+3
// (and output dims tx*4..+3). K stored transposed in smem (stride 66).
// P kept in registers; redistributed for PV via warp shuffles (c uniform).
// ---------------------------------------------------------------------------
#define KT_STRIDE 66

__global__ __launch_bounds__(256, 2) void attn2(
    const float* __restrict__ Q, const float* __restrict__ K,
    const float* __restrict__ V, const int* __restrict__ mask,
    float* __restrict__ O)
{
    extern __shared__ float smem[];
    float* Qs  = smem;                 // 128*64
    float* KsT = Qs + 128 * 64;        // 64*66
    float* Vs  = KsT + 64 * KT_STRIDE; // 64*64

    const int qt = blockIdx.x, h = blockIdx.y, b = blockIdx.z;
    const int tid = threadIdx.x;
    const int tx = tid & 15, ty = tid >> 4, lane = tid & 31;
    const size_t hoff = (size_t)h * DK;
    const size_t qrow0 = (size_t)b * SEQ + qt * 128;

    // Load Q tile (scaled by 1/sqrt(64))
    #pragma unroll
    for (int it = 0; it < 8; it++) {
        int idx = tid + it * 256;
        int r = idx >> 4;
        int c4 = (idx & 15) << 2;
        float4 v = *(const float4*)(Q + (qrow0 + r) * DMODEL + hoff + c4);
        v.x *= 0.125f; v.y *= 0.125f; v.z *= 0.125f; v.w *= 0.125f;
        *(float4*)&Qs[r * 64 + c4] = v;
    }

    float m[8], l[8];
    float2 o2[8][2];
    #pragma unroll
    for (int i = 0; i < 8; i++) {
        m[i] = -INFINITY; l[i] = 0.f;
        o2[i][0] = make_float2(0.f, 0.f);
        o2[i][1] = make_float2(0.f, 0.f);
    }

    for (int kt = 0; kt < 32; kt++) {
        __syncthreads();   // previous tile fully consumed (also covers Qs store)

        // Load K tile transposed: KsT[d][c]
        {
            const int c = tid >> 2, t4 = tid & 3;
            const float* kg = K + ((size_t)b * SEQ + kt * 64 + c) * DMODEL + hoff + t4 * 16;
            #pragma unroll
            for (int q4 = 0; q4 < 4; q4++) {
                float4 v = *(const float4*)(kg + q4 * 4);
                int d = t4 * 16 + q4 * 4;
                KsT[(d + 0) * KT_STRIDE + c] = v.x;
                KsT[(d + 1) * KT_STRIDE + c] = v.y;
                KsT[(d + 2) * KT_STRIDE + c] = v.z;
                KsT[(d + 3) * KT_STRIDE + c] = v.w;
            }
        }
        // Load V tile (natural layout)
        #pragma unroll
        for (int it = 0; it < 4; it++) {
            int idx = tid + it * 256;
            int r = idx >> 4;
            int c4 = (idx & 15) << 2;
            *(float4*)&Vs[r * 64 + c4] =
                *(const float4*)(V + ((size_t)b * SEQ + kt * 64 + r) * DMODEL + hoff + c4);
        }
        __syncthreads();

        // ---- QK^T: s[8 rows][4 cols] with f32x2 ----
        float2 s2[8][2];
        #pragma unroll
        for (int i = 0; i < 8; i++) {
            s2[i][0] = make_float2(0.f, 0.f);
            s2[i][1] = make_float2(0.f, 0.f);
        }
        #pragma unroll
        for (int d0 = 0; d0 < 64; d0 += 4) {
            float2 k2[4][2];
            #pragma unroll
            for (int dd = 0; dd < 4; dd++) {
                k2[dd][0] = *(float2*)&KsT[(d0 + dd) * KT_STRIDE + tx * 4];
                k2[dd][1] = *(float2*)&KsT[(d0 + dd) * KT_STRIDE + tx * 4 + 2];
            }
            #pragma unroll
            for (int i = 0; i < 8; i++) {
                float4 qv = *(const float4*)&Qs[(ty * 8 + i) * 64 + d0];
                float2 q;
                q = make_float2(qv.x, qv.x); ffma2(s2[i][0], q, k2[0][0]); ffma2(s2[i][1], q, k2[0][1]);
                q = make_float2(qv.y, qv.y); ffma2(s2[i][0], q, k2[1][0]); ffma2(s2[i][1], q, k2[1][1]);
                q = make_float2(qv.z, qv.z); ffma2(s2[i][0], q, k2[2][0]); ffma2(s2[i][1], q, k2[2][1]);
                q = make_float2(qv.w, qv.w); ffma2(s2[i][0], q, k2[3][0]); ffma2(s2[i][1], q, k2[3][1]);
            }
        }

        // ---- Mask (src_mask[b,0,0,key]==0 -> -inf) ----
        {
            int4 mv = *(const int4*)(mask + (size_t)b * SEQ + kt * 64 + tx * 4);
            float f0 = (mv.x == 0) ? -INFINITY : 0.f;
            float f1 = (mv.y == 0) ? -INFINITY : 0.f;
            float f2 = (mv.z == 0) ? -INFINITY : 0.f;
            float f3 = (mv.w == 0) ? -INFINITY : 0.f;
            #pragma unroll
            for (int i = 0; i < 8; i++) {
                s2[i][0].x += f0;
                s2[i][0].y += f1;
                s2[i][1].x += f2;
                s2[i][1].y += f3;
            }
        }

        // ---- Online softmax per row (16-lane reductions) ----
        #pragma unroll
        for (int i = 0; i < 8; i++) {
            float mx = fmaxf(fmaxf(s2[i][0].x, s2[i][0].y), fmaxf(s2[i][1].x, s2[i][1].y));
            mx = fmaxf(mx, __shfl_xor_sync(0xffffffffu, mx, 1));
            mx = fmaxf(mx, __shfl_xor_sync(0xffffffffu, mx, 2));
            mx = fmaxf(mx, __shfl_xor_sync(0xffffffffu, mx, 4));
            mx = fmaxf(mx, __shfl_xor_sync(0xffffffffu, mx, 8));
            float mn = fmaxf(m[i], mx);
            float corr = __expf(m[i] - mn);   // m=-inf, mn finite -> 0
            s2[i][0].x = __expf(s2[i][0].x - mn);
            s2[i][0].y = __expf(s2[i][0].y - mn);
            s2[i][1].x = __expf(s2[i][1].x - mn);
            s2[i][1].y = __expf(s2[i][1].y - mn);
            float rs = s2[i][0].x + s2[i][0].y + s2[i][1].x + s2[i][1].y;
            rs += __shfl_xor_sync(0xffffffffu, rs, 1);
            rs += __shfl_xor_sync(0xffffffffu, rs, 2);
            rs += __shfl_xor_sync(0xffffffffu, rs, 4);
            rs += __shfl_xor_sync(0xffffffffu, rs, 8);
            l[i] = l[i] * corr + rs;
            m[i] = mn;
            o2[i][0].x *= corr; o2[i][0].y *= corr;
            o2[i][1].x *= corr; o2[i][1].y *= corr;
        }

        // ---- PV: O += P @ V  (P redistributed via shuffles; c uniform) ----
        #pragma unroll
        for (int u2 = 0; u2 < 2; u2++) {
            #pragma unroll
            for (int cm = 0; cm < 2; cm++) {
                #pragma unroll
                for (int tc = 0; tc < 16; tc++) {
                    const int c = tc * 4 + u2 * 2 + cm;
                    const int src = (lane & 16) | tc;
                    float2 v0 = *(float2*)&Vs[c * 64 + tx * 4];
                    float2 v1 = *(float2*)&Vs[c * 64 + tx * 4 + 2];
                    #pragma unroll
                    for (int i = 0; i < 8; i++) {
                        float pv = cm ? s2[i][u2].y : s2[i][u2].x;
                        float pc = __shfl_sync(0xffffffffu, pv, src);
                        float2 p2 = make_float2(pc, pc);
                        ffma2(o2[i][0], p2, v0);
                        ffma2(o2[i][1], p2, v1);
                    }
                }
            }
        }
    }

    // Write output
    #pragma unroll
    for (int i = 0; i < 8; i++) {
        float inv = 1.f / l[i];
        float4 ov = make_float4(o2[i][0].x * inv, o2[i][0].y * inv,
                                o2[i][1].x * inv, o2[i][1].y * inv);
        *(float4*)(O + (qrow0 + ty * 8 + i) * DMODEL + hoff + tx * 4) = ov;
    }
}

// ---------------------------------------------------------------------------
// out[row] = LayerNorm(a[row] + b[row]) * gamma + beta, one block per row.
// ---------------------------------------------------------------------------
__global__ __launch_bounds__(256) void add_ln_kernel(
    const float* __restrict__ a, const float* __restrict__ bsrc,
    const float* __restrict__ g, const float* __restrict__ be,
    float* __restrict__ out)
{
    const int row = blockIdx.x;
    const int tid = threadIdx.x;
    const float* pa = a + (size_t)row * DMODEL;
    const float* pb = bsrc + (size_t)row * DMODEL;

    float v[4];
    float sum = 0.f, sq = 0.f;
    #pragma unroll
    for (int i = 0; i < 4; i++) {
        int c = tid + i * 256;
        float x = pa[c] + pb[c];
        v[i] = x;
        sum += x;
        sq += x * x;
    }
    #pragma unroll
    for (int o = 16; o > 0; o >>= 1) {
        sum += __shfl_xor_sync(0xffffffffu, sum, o);
        sq  += __shfl_xor_sync(0xffffffffu, sq,  o);
    }
    __shared__ float ssum[8], ssq[8];
    if ((tid & 31) == 0) { ssum[tid >> 5] = sum; ssq[tid >> 5] = sq; }
    __syncthreads();
    if (tid < 32) {
        float s2 = (tid < 8) ? ssum[tid] : 0.f;
        float q2 = (tid < 8) ? ssq[tid] : 0.f;
        #pragma unroll
        for (int o = 4; o > 0; o >>= 1) {
            s2 += __shfl_xor_sync(0xffffffffu, s2, o);
            q2 += __shfl_xor_sync(0xffffffffu, q2, o);
        }
        if (tid == 0) { ssum[0] = s2; ssq[0] = q2; }
    }
    __syncthreads();
    const float mu   = ssum[0] * (1.f / DMODEL);
    const float var  = ssq[0] * (1.f / DMODEL) - mu * mu;
    const float rstd = rsqrtf(var + 1e-5f);

    float* po = out + (size_t)row * DMODEL;
    #pragma unroll
    for (int i = 0; i < 4; i++) {
        int c = tid + i * 256;
        po[c] = (v[i] - mu) * rstd * g[c] + be[c];
    }
}

// ---------------------------------------------------------------------------
// Launch
// ---------------------------------------------------------------------------
extern "C" void kernel_launch(void* const* d_in, const int* in_sizes, int n_in,
                              void* d_out, int out_size)
{
    (void)in_sizes; (void)n_in; (void)out_size;
    const float* x    = (const float*)d_in[0];
    const int*   mask = (const int*)  d_in[1];
    const float* w_q  = (const float*)d_in[2];
    const float* b_q  = (const float*)d_in[3];
    const float* w_k  = (const float*)d_in[4];
    const float* b_k  = (const float*)d_in[5];
    const float* w_v  = (const float*)d_in[6];
    const float* b_v  = (const float*)d_in[7];
    const float* w_o  = (const float*)d_in[8];
    const float* b_o  = (const float*)d_in[9];
    const float* w1   = (const float*)d_in[10];
    const float* b1   = (const float*)d_in[11];
    const float* w2   = (const float*)d_in[12];
    const float* b2   = (const float*)d_in[13];
    const float* g1   = (const float*)d_in[14];
    const float* be1  = (const float*)d_in[15];
    const float* g2   = (const float*)d_in[16];
    const float* be2  = (const float*)d_in[17];

    float *q, *k, *v, *ctx, *t1, *h, *ff;
    cudaGetSymbolAddress((void**)&q,   g_q);
    cudaGetSymbolAddress((void**)&k,   g_k);
    cudaGetSymbolAddress((void**)&v,   g_v);
    cudaGetSymbolAddress((void**)&ctx, g_ctx);
    cudaGetSymbolAddress((void**)&t1,  g_t1);
    cudaGetSymbolAddress((void**)&h,   g_h);
    cudaGetSymbolAddress((void**)&ff,  g_ff);

    const int attn_smem = (128 * 64 + 64 * KT_STRIDE + 64 * 64) * 4;  // 66048 B
    cudaFuncSetAttribute(attn2, cudaFuncAttributeMaxDynamicSharedMemorySize, attn_smem);

    dim3 blk(256);
    dim3 gProj(DMODEL / 128, MROWS / 128);   // (8, 64)
    dim3 gFF1(DFF / 128, MROWS / 128);       // (32, 64)
    dim3 gAtt(SEQ / 128, NHEADS, BATCH);     // (16, 16, 4)

    gemm_tf32<<<gProj, blk>>>(MROWS, DMODEL, DMODEL, x, w_q, b_q, q, 0);
    gemm_tf32<<<gProj, blk>>>(MROWS, DMODEL, DMODEL, x, w_k, b_k, k, 0);
    gemm_tf32<<<gProj, blk>>>(MROWS, DMODEL, DMODEL, x, w_v, b_v, v, 0);

    attn2<<<gAtt, blk, attn_smem>>>(q, k, v, mask, ctx);

    gemm_tf32<<<gProj, blk>>>(MROWS, DMODEL, DMODEL, ctx, w_o, b_o, t1, 0);
    add_ln_kernel<<<MROWS, 256>>>(x, t1, g1, be1, h);

    gemm_tf32<<<gFF1, blk>>>(MROWS, DFF, DMODEL, h, w1, b1, ff, 1);
    gemm_tf32<<<gProj, blk>>>(MROWS, DMODEL, DFF, ff, w2, b2, t1, 0);
    add_ln_kernel<<<MROWS, 256>>>(h, t1, g2, be2, (float*)d_out);
}

// round 5
// speedup vs baseline: 4.0508x; 1.4740x over previous
#include <cuda_runtime.h>
#include <math.h>

// ---------------------------------------------------------------------------
// Problem constants
// ---------------------------------------------------------------------------
#define BATCH 4
#define SEQ   2048
#define DMODEL 1024
#define NHEADS 16
#define DK    64
#define DFF   4096
#define MROWS (BATCH * SEQ)   // 8192

// ---------------------------------------------------------------------------
// Scratch (no cudaMalloc allowed)
// ---------------------------------------------------------------------------
__device__ float g_q  [MROWS * DMODEL];
__device__ float g_k  [MROWS * DMODEL];
__device__ float g_v  [MROWS * DMODEL];
__device__ float g_ctx[MROWS * DMODEL];
__device__ float g_t1 [MROWS * DMODEL];
__device__ float g_h  [MROWS * DMODEL];
__device__ float g_ff [MROWS * DFF];

// ---------------------------------------------------------------------------
// Helpers
// ---------------------------------------------------------------------------
__device__ __forceinline__ unsigned cvt_tf32(float x) {
    unsigned r;
    asm("cvt.rna.tf32.f32 %0, %1;" : "=r"(r) : "f"(x));
    return r;
}

__device__ __forceinline__ void mma_tf32(float* c, const unsigned* a, const unsigned* b) {
    asm volatile(
        "mma.sync.aligned.m16n8k8.row.col.f32.tf32.tf32.f32 "
        "{%0,%1,%2,%3}, {%4,%5,%6,%7}, {%8,%9}, {%0,%1,%2,%3};"
        : "+f"(c[0]), "+f"(c[1]), "+f"(c[2]), "+f"(c[3])
        : "r"(a[0]), "r"(a[1]), "r"(a[2]), "r"(a[3]), "r"(b[0]), "r"(b[1]));
}

// ---------------------------------------------------------------------------
// TF32 tensor-core GEMM: C[M,N] = A[M,K] @ B[K,N] + bias[N] (optional ReLU)
// BM=BN=128, BK=32, 256 threads = 8 warps (2x4), warp tile 64x32.
// ---------------------------------------------------------------------------
#define AS_STRIDE 36
#define BS_STRIDE 132

__global__ __launch_bounds__(256) void gemm_tf32(
    int M, int N, int K,
    const float* __restrict__ A, const float* __restrict__ B,
    const float* __restrict__ bias, float* __restrict__ C, int relu)
{
    __shared__ unsigned As[128 * AS_STRIDE];
    __shared__ unsigned Bs[32 * BS_STRIDE];

    const int tid  = threadIdx.x;
    const int lane = tid & 31;
    const int warp = tid >> 5;
    const int wm = (warp >> 2) * 64;   // warp row offset within block (0 / 64)
    const int wn = (warp & 3) * 32;    // warp col offset (0/32/64/96)
    const int g = lane >> 2;           // 0..7
    const int t = lane & 3;            // 0..3
    const int cRow = blockIdx.y, cCol = blockIdx.x;

    const int aRow = tid >> 3;         // 0..31
    const int aCol = (tid & 7) * 4;    // 0..28
    const int bRow = tid >> 5;         // 0..7
    const int bCol = (tid & 31) * 4;   // 0..124

    const float* Ag = A + (size_t)(cRow * 128) * K;
    const float* Bg = B + cCol * 128;

    float acc[4][4][4];
    #pragma unroll
    for (int i = 0; i < 4; i++)
        #pragma unroll
        for (int j = 0; j < 4; j++)
            #pragma unroll
            for (int e = 0; e < 4; e++) acc[i][j][e] = 0.f;

    for (int k0 = 0; k0 < K; k0 += 32) {
        #pragma unroll
        for (int r = 0; r < 4; r++) {
            float4 v = *(const float4*)(Ag + (size_t)(aRow + r * 32) * K + k0 + aCol);
            uint4 u = make_uint4(cvt_tf32(v.x), cvt_tf32(v.y), cvt_tf32(v.z), cvt_tf32(v.w));
            *(uint4*)&As[(aRow + r * 32) * AS_STRIDE + aCol] = u;
        }
        #pragma unroll
        for (int r = 0; r < 4; r++) {
            float4 v = *(const float4*)(Bg + (size_t)(k0 + bRow + r * 8) * N + bCol);
            uint4 u = make_uint4(cvt_tf32(v.x), cvt_tf32(v.y), cvt_tf32(v.z), cvt_tf32(v.w));
            *(uint4*)&Bs[(bRow + r * 8) * BS_STRIDE + bCol] = u;
        }
        __syncthreads();

        #pragma unroll
        for (int k8 = 0; k8 < 4; k8++) {
            const int kb = k8 * 8;
            unsigned af[4][4], bf[4][2];
            #pragma unroll
            for (int tm = 0; tm < 4; tm++) {
                int r0 = (wm + tm * 16 + g) * AS_STRIDE;
                af[tm][0] = As[r0 + kb + t];
                af[tm][1] = As[r0 + 8 * AS_STRIDE + kb + t];
                af[tm][2] = As[r0 + kb + 4 + t];
                af[tm][3] = As[r0 + 8 * AS_STRIDE + kb + 4 + t];
            }
            #pragma unroll
            for (int tn = 0; tn < 4; tn++) {
                bf[tn][0] = Bs[(kb + t) * BS_STRIDE + wn + tn * 8 + g];
                bf[tn][1] = Bs[(kb + 4 + t) * BS_STRIDE + wn + tn * 8 + g];
            }
            #pragma unroll
            for (int tm = 0; tm < 4; tm++)
                #pragma unroll
                for (int tn = 0; tn < 4; tn++)
                    mma_tf32(acc[tm][tn], af[tm], bf[tn]);
        }
        __syncthreads();
    }

    #pragma unroll
    for (int tm = 0; tm < 4; tm++) {
        #pragma unroll
        for (int tn = 0; tn < 4; tn++) {
            int row = cRow * 128 + wm + tm * 16 + g;
            int col = cCol * 128 + wn + tn * 8 + 2 * t;
            float2 bb = *(const float2*)(bias + col);
            float2 v0 = make_float2(acc[tm][tn][0] + bb.x, acc[tm][tn][1] + bb.y);
            float2 v1 = make_float2(acc[tm][tn][2] + bb.x, acc[tm][tn][3] + bb.y);
            if (relu) {
                v0.x = fmaxf(v0.x, 0.f); v0.y = fmaxf(v0.y, 0.f);
                v1.x = fmaxf(v1.x, 0.f); v1.y = fmaxf(v1.y, 0.f);
            }
            *(float2*)(C + (size_t)row * N + col) = v0;
            *(float2*)(C + (size_t)(row + 8) * N + col) = v1;
        }
    }
}

// ---------------------------------------------------------------------------
// Flash attention on tensor cores (tf32 mma.sync m16n8k8).
// Block = (batch, head, 128-row Q tile); 256 threads = 8 warps.
// Warp w owns q-rows [16w, 16w+16). Q fragments live in registers for the
// whole KV sweep. Scores/O accumulate in mma layout (rows g/g+8, cols 2t/2t+1).
// P is remapped from accumulator layout to A-fragment layout with shuffles.
// ---------------------------------------------------------------------------
#define QS_STRIDE 68
#define KS_STRIDE 68
#define VS_STRIDE 72
#define ATTN_SMEM_BYTES (64 * KS_STRIDE * 4 + 64 * VS_STRIDE * 4 + 256)

__global__ __launch_bounds__(256, 2) void attn3(
    const float* __restrict__ Q, const float* __restrict__ K,
    const float* __restrict__ V, const int* __restrict__ mask,
    float* __restrict__ O)
{
    extern __shared__ char smc[];
    float*    Qstage = (float*)smc;                         // 128*68 floats (staging only)
    unsigned* Ks     = (unsigned*)smc;                      // 64*68 tf32
    unsigned* Vs     = (unsigned*)(smc + 64 * KS_STRIDE * 4); // 64*72 tf32
    float*    maskf  = (float*)(smc + 64 * KS_STRIDE * 4 + 64 * VS_STRIDE * 4);

    const int qt = blockIdx.x, h = blockIdx.y, b = blockIdx.z;
    const int tid  = threadIdx.x;
    const int lane = tid & 31;
    const int warp = tid >> 5;
    const int g = lane >> 2;   // 0..7
    const int t = lane & 3;    // 0..3
    const size_t hoff = (size_t)h * DK;
    const size_t qrow0 = (size_t)b * SEQ + qt * 128;

    // ---- Stage Q (scaled) then extract per-warp fragments into registers ----
    #pragma unroll
    for (int it = 0; it < 8; it++) {
        int idx = tid + it * 256;
        int r = idx >> 4;
        int c4 = (idx & 15) << 2;
        float4 v = *(const float4*)(Q + (qrow0 + r) * DMODEL + hoff + c4);
        v.x *= 0.125f; v.y *= 0.125f; v.z *= 0.125f; v.w *= 0.125f;
        *(float4*)&Qstage[r * QS_STRIDE + c4] = v;
    }
    __syncthreads();

    unsigned qf[8][4];
    {
        const int r0 = warp * 16;
        #pragma unroll
        for (int kk = 0; kk < 8; kk++) {
            qf[kk][0] = cvt_tf32(Qstage[(r0 + g)     * QS_STRIDE + kk * 8 + t]);
            qf[kk][1] = cvt_tf32(Qstage[(r0 + 8 + g) * QS_STRIDE + kk * 8 + t]);
            qf[kk][2] = cvt_tf32(Qstage[(r0 + g)     * QS_STRIDE + kk * 8 + 4 + t]);
            qf[kk][3] = cvt_tf32(Qstage[(r0 + 8 + g) * QS_STRIDE + kk * 8 + 4 + t]);
        }
    }
    __syncthreads();   // Qstage dead; smem becomes Ks/Vs

    float m0 = -INFINITY, m1 = -INFINITY, l0 = 0.f, l1 = 0.f;
    float oacc[8][4];
    #pragma unroll
    for (int j = 0; j < 8; j++)
        #pragma unroll
        for (int e = 0; e < 4; e++) oacc[j][e] = 0.f;

    for (int kt = 0; kt < 32; kt++) {
        const size_t kvbase = ((size_t)b * SEQ + kt * 64) * DMODEL + hoff;

        // ---- Load K, V tiles (convert to tf32 at store) ----
        #pragma unroll
        for (int it = 0; it < 4; it++) {
            int idx = tid + it * 256;
            int r = idx >> 4;
            int c4 = (idx & 15) << 2;
            float4 kv = *(const float4*)(K + kvbase + (size_t)r * DMODEL + c4);
            uint4 ku = make_uint4(cvt_tf32(kv.x), cvt_tf32(kv.y), cvt_tf32(kv.z), cvt_tf32(kv.w));
            *(uint4*)&Ks[r * KS_STRIDE + c4] = ku;
            float4 vv = *(const float4*)(V + kvbase + (size_t)r * DMODEL + c4);
            uint4 vu = make_uint4(cvt_tf32(vv.x), cvt_tf32(vv.y), cvt_tf32(vv.z), cvt_tf32(vv.w));
            *(uint4*)&Vs[r * VS_STRIDE + c4] = vu;
        }
        if (tid < 64)
            maskf[tid] = (mask[(size_t)b * SEQ + kt * 64 + tid] == 0) ? -INFINITY : 0.f;
        __syncthreads();

        // ---- S = Q @ K^T (64 mma/warp) ----
        float sacc[8][4];
        #pragma unroll
        for (int j = 0; j < 8; j++)
            #pragma unroll
            for (int e = 0; e < 4; e++) sacc[j][e] = 0.f;

        #pragma unroll
        for (int kk = 0; kk < 8; kk++) {
            #pragma unroll
            for (int nj = 0; nj < 8; nj++) {
                unsigned bf[2];
                bf[0] = Ks[(nj * 8 + g) * KS_STRIDE + kk * 8 + t];
                bf[1] = Ks[(nj * 8 + g) * KS_STRIDE + kk * 8 + 4 + t];
                mma_tf32(sacc[nj], qf[kk], bf);
            }
        }

        // ---- Mask ----
        #pragma unroll
        for (int nj = 0; nj < 8; nj++) {
            float mk0 = maskf[nj * 8 + 2 * t];
            float mk1 = maskf[nj * 8 + 2 * t + 1];
            sacc[nj][0] += mk0; sacc[nj][1] += mk1;
            sacc[nj][2] += mk0; sacc[nj][3] += mk1;
        }

        // ---- Online softmax (rows g and g+8) ----
        {
            float mx0 = -INFINITY, mx1 = -INFINITY;
            #pragma unroll
            for (int nj = 0; nj < 8; nj++) {
                mx0 = fmaxf(mx0, fmaxf(sacc[nj][0], sacc[nj][1]));
                mx1 = fmaxf(mx1, fmaxf(sacc[nj][2], sacc[nj][3]));
            }
            mx0 = fmaxf(mx0, __shfl_xor_sync(0xffffffffu, mx0, 1));
            mx0 = fmaxf(mx0, __shfl_xor_sync(0xffffffffu, mx0, 2));
            mx1 = fmaxf(mx1, __shfl_xor_sync(0xffffffffu, mx1, 1));
            mx1 = fmaxf(mx1, __shfl_xor_sync(0xffffffffu, mx1, 2));
            float mn0 = fmaxf(m0, mx0), mn1 = fmaxf(m1, mx1);
            float corr0 = __expf(m0 - mn0), corr1 = __expf(m1 - mn1);

            float rs0 = 0.f, rs1 = 0.f;
            #pragma unroll
            for (int nj = 0; nj < 8; nj++) {
                sacc[nj][0] = __expf(sacc[nj][0] - mn0);
                sacc[nj][1] = __expf(sacc[nj][1] - mn0);
                sacc[nj][2] = __expf(sacc[nj][2] - mn1);
                sacc[nj][3] = __expf(sacc[nj][3] - mn1);
                rs0 += sacc[nj][0] + sacc[nj][1];
                rs1 += sacc[nj][2] + sacc[nj][3];
            }
            rs0 += __shfl_xor_sync(0xffffffffu, rs0, 1);
            rs0 += __shfl_xor_sync(0xffffffffu, rs0, 2);
            rs1 += __shfl_xor_sync(0xffffffffu, rs1, 1);
            rs1 += __shfl_xor_sync(0xffffffffu, rs1, 2);
            l0 = l0 * corr0 + rs0;  m0 = mn0;
            l1 = l1 * corr1 + rs1;  m1 = mn1;
            #pragma unroll
            for (int j = 0; j < 8; j++) {
                oacc[j][0] *= corr0; oacc[j][1] *= corr0;
                oacc[j][2] *= corr1; oacc[j][3] *= corr1;
            }
        }

        // ---- O += P @ V : remap P accum->A-frag via shuffles, then mma ----
        {
            const int src_lo = (lane & ~3) | (t >> 1);  // holder of col t
            const int src_hi = src_lo + 2;              // holder of col t+4
            const bool odd = (t & 1);
            #pragma unroll
            for (int j = 0; j < 8; j++) {
                float c0a = __shfl_sync(0xffffffffu, sacc[j][0], src_lo);
                float c1a = __shfl_sync(0xffffffffu, sacc[j][1], src_lo);
                float c0b = __shfl_sync(0xffffffffu, sacc[j][0], src_hi);
                float c1b = __shfl_sync(0xffffffffu, sacc[j][1], src_hi);
                float c2a = __shfl_sync(0xffffffffu, sacc[j][2], src_lo);
                float c3a = __shfl_sync(0xffffffffu, sacc[j][3], src_lo);
                float c2b = __shfl_sync(0xffffffffu, sacc[j][2], src_hi);
                float c3b = __shfl_sync(0xffffffffu, sacc[j][3], src_hi);
                unsigned af[4];
                af[0] = cvt_tf32(odd ? c1a : c0a);   // P[g][8j+t]
                af[1] = cvt_tf32(odd ? c3a : c2a);   // P[g+8][8j+t]
                af[2] = cvt_tf32(odd ? c1b : c0b);   // P[g][8j+t+4]
                af[3] = cvt_tf32(odd ? c3b : c2b);   // P[g+8][8j+t+4]
                #pragma unroll
                for (int jj = 0; jj < 8; jj++) {
                    unsigned bf[2];
                    bf[0] = Vs[(j * 8 + t)     * VS_STRIDE + jj * 8 + g];
                    bf[1] = Vs[(j * 8 + t + 4) * VS_STRIDE + jj * 8 + g];
                    mma_tf32(oacc[jj], af, bf);
                }
            }
        }
        __syncthreads();   // tile consumed; safe to overwrite next iteration
    }

    // ---- Output: divide by l, write float2 per (row, dim-pair) ----
    {
        const float inv0 = 1.f / l0, inv1 = 1.f / l1;
        const size_t r0 = qrow0 + warp * 16 + g;
        #pragma unroll
        for (int jj = 0; jj < 8; jj++) {
            int col = jj * 8 + 2 * t;
            *(float2*)(O + r0 * DMODEL + hoff + col) =
                make_float2(oacc[jj][0] * inv0, oacc[jj][1] * inv0);
            *(float2*)(O + (r0 + 8) * DMODEL + hoff + col) =
                make_float2(oacc[jj][2] * inv1, oacc[jj][3] * inv1);
        }
    }
}

// ---------------------------------------------------------------------------
// out[row] = LayerNorm(a[row] + b[row]) * gamma + beta, one block per row.
// ---------------------------------------------------------------------------
__global__ __launch_bounds__(256) void add_ln_kernel(
    const float* __restrict__ a, const float* __restrict__ bsrc,
    const float* __restrict__ g, const float* __restrict__ be,
    float* __restrict__ out)
{
    const int row = blockIdx.x;
    const int tid = threadIdx.x;
    const float* pa = a + (size_t)row * DMODEL;
    const float* pb = bsrc + (size_t)row * DMODEL;

    float v[4];
    float sum = 0.f, sq = 0.f;
    #pragma unroll
    for (int i = 0; i < 4; i++) {
        int c = tid + i * 256;
        float x = pa[c] + pb[c];
        v[i] = x;
        sum += x;
        sq += x * x;
    }
    #pragma unroll
    for (int o = 16; o > 0; o >>= 1) {
        sum += __shfl_xor_sync(0xffffffffu, sum, o);
        sq  += __shfl_xor_sync(0xffffffffu, sq,  o);
    }
    __shared__ float ssum[8], ssq[8];
    if ((tid & 31) == 0) { ssum[tid >> 5] = sum; ssq[tid >> 5] = sq; }
    __syncthreads();
    if (tid < 32) {
        float s2 = (tid < 8) ? ssum[tid] : 0.f;
        float q2 = (tid < 8) ? ssq[tid] : 0.f;
        #pragma unroll
        for (int o = 4; o > 0; o >>= 1) {
            s2 += __shfl_xor_sync(0xffffffffu, s2, o);
            q2 += __shfl_xor_sync(0xffffffffu, q2, o);
        }
        if (tid == 0) { ssum[0] = s2; ssq[0] = q2; }
    }
    __syncthreads();
    const float mu   = ssum[0] * (1.f / DMODEL);
    const float var  = ssq[0] * (1.f / DMODEL) - mu * mu;
    const float rstd = rsqrtf(var + 1e-5f);

    float* po = out + (size_t)row * DMODEL;
    #pragma unroll
    for (int i = 0; i < 4; i++) {
        int c = tid + i * 256;
        po[c] = (v[i] - mu) * rstd * g[c] + be[c];
    }
}

// ---------------------------------------------------------------------------
// Launch
// ---------------------------------------------------------------------------
extern "C" void kernel_launch(void* const* d_in, const int* in_sizes, int n_in,
                              void* d_out, int out_size)
{
    (void)in_sizes; (void)n_in; (void)out_size;
    const float* x    = (const float*)d_in[0];
    const int*   mask = (const int*)  d_in[1];
    const float* w_q  = (const float*)d_in[2];
    const float* b_q  = (const float*)d_in[3];
    const float* w_k  = (const float*)d_in[4];
    const float* b_k  = (const float*)d_in[5];
    const float* w_v  = (const float*)d_in[6];
    const float* b_v  = (const float*)d_in[7];
    const float* w_o  = (const float*)d_in[8];
    const float* b_o  = (const float*)d_in[9];
    const float* w1   = (const float*)d_in[10];
    const float* b1   = (const float*)d_in[11];
    const float* w2   = (const float*)d_in[12];
    const float* b2   = (const float*)d_in[13];
    const float* g1   = (const float*)d_in[14];
    const float* be1  = (const float*)d_in[15];
    const float* g2   = (const float*)d_in[16];
    const float* be2  = (const float*)d_in[17];

    float *q, *k, *v, *ctx, *t1, *h, *ff;
    cudaGetSymbolAddress((void**)&q,   g_q);
    cudaGetSymbolAddress((void**)&k,   g_k);
    cudaGetSymbolAddress((void**)&v,   g_v);
    cudaGetSymbolAddress((void**)&ctx, g_ctx);
    cudaGetSymbolAddress((void**)&t1,  g_t1);
    cudaGetSymbolAddress((void**)&h,   g_h);
    cudaGetSymbolAddress((void**)&ff,  g_ff);

    cudaFuncSetAttribute(attn3, cudaFuncAttributeMaxDynamicSharedMemorySize,
                         ATTN_SMEM_BYTES);

    dim3 blk(256);
    dim3 gProj(DMODEL / 128, MROWS / 128);   // (8, 64)
    dim3 gFF1(DFF / 128, MROWS / 128);       // (32, 64)
    dim3 gAtt(SEQ / 128, NHEADS, BATCH);     // (16, 16, 4)

    gemm_tf32<<<gProj, blk>>>(MROWS, DMODEL, DMODEL, x, w_q, b_q, q, 0);
    gemm_tf32<<<gProj, blk>>>(MROWS, DMODEL, DMODEL, x, w_k, b_k, k, 0);
    gemm_tf32<<<gProj, blk>>>(MROWS, DMODEL, DMODEL, x, w_v, b_v, v, 0);

    attn3<<<gAtt, blk, ATTN_SMEM_BYTES>>>(q, k, v, mask, ctx);

    gemm_tf32<<<gProj, blk>>>(MROWS, DMODEL, DMODEL, ctx, w_o, b_o, t1, 0);
    add_ln_kernel<<<MROWS, 256>>>(x, t1, g1, be1, h);

    gemm_tf32<<<gFF1, blk>>>(MROWS, DFF, DMODEL, h, w1, b1, ff, 1);
    gemm_tf32<<<gProj, blk>>>(MROWS, DMODEL, DFF, ff, w2, b2, t1, 0);
    add_ln_kernel<<<MROWS, 256>>>(h, t1, g2, be2, (float*)d_out);
}

// round 6
// speedup vs baseline: 4.2826x; 1.0572x over previous
#include <cuda_runtime.h>
#include <math.h>

// ---------------------------------------------------------------------------
// Problem constants
// ---------------------------------------------------------------------------
#define BATCH 4
#define SEQ   2048
#define DMODEL 1024
#define NHEADS 16
#define DK    64
#define DFF   4096
#define MROWS (BATCH * SEQ)   // 8192

// ---------------------------------------------------------------------------
// Scratch (no cudaMalloc allowed)
// ---------------------------------------------------------------------------
__device__ float g_q  [MROWS * DMODEL];
__device__ float g_k  [MROWS * DMODEL];
__device__ float g_v  [MROWS * DMODEL];
__device__ float g_ctx[MROWS * DMODEL];
__device__ float g_t1 [MROWS * DMODEL];
__device__ float g_h  [MROWS * DMODEL];
__device__ float g_ff [MROWS * DFF];

// ---------------------------------------------------------------------------
// Helpers
// ---------------------------------------------------------------------------
__device__ __forceinline__ unsigned cvt_tf32(float x) {
    unsigned r;
    asm("cvt.rna.tf32.f32 %0, %1;" : "=r"(r) : "f"(x));
    return r;
}

__device__ __forceinline__ void mma_tf32(float* c, const unsigned* a, const unsigned* b) {
    asm volatile(
        "mma.sync.aligned.m16n8k8.row.col.f32.tf32.tf32.f32 "
        "{%0,%1,%2,%3}, {%4,%5,%6,%7}, {%8,%9}, {%0,%1,%2,%3};"
        : "+f"(c[0]), "+f"(c[1]), "+f"(c[2]), "+f"(c[3])
        : "r"(a[0]), "r"(a[1]), "r"(a[2]), "r"(a[3]), "r"(b[0]), "r"(b[1]));
}

__device__ __forceinline__ void cp_async16(void* smem_dst, const void* gmem_src) {
    unsigned saddr = (unsigned)__cvta_generic_to_shared(smem_dst);
    asm volatile("cp.async.cg.shared.global [%0], [%1], 16;"
                 :: "r"(saddr), "l"(gmem_src));
}
#define CP_COMMIT() asm volatile("cp.async.commit_group;")
#define CP_WAIT(n)  asm volatile("cp.async.wait_group %0;" :: "n"(n))

// ---------------------------------------------------------------------------
// TF32 tensor-core GEMM with 2-stage cp.async pipeline.
// C[M,N] = A[M,K] @ B[K,N] + bias[N] (optional ReLU)
// BM=BN=128, BK=32, 256 threads = 8 warps (2x4), warp tile 64x32.
// Raw fp32 bits are fed to mma.tf32 (HW truncates mantissa; no cvt needed).
// ---------------------------------------------------------------------------
#define AS_STRIDE 36
#define BS_STRIDE 132
#define STAGE_FLOATS (128 * AS_STRIDE + 32 * BS_STRIDE)
#define GEMM_SMEM_BYTES (2 * STAGE_FLOATS * 4)

__global__ __launch_bounds__(256) void gemm_tf32(
    int M, int N, int K,
    const float* __restrict__ A, const float* __restrict__ B,
    const float* __restrict__ bias, float* __restrict__ C, int relu)
{
    extern __shared__ float sm[];

    const int tid  = threadIdx.x;
    const int lane = tid & 31;
    const int warp = tid >> 5;
    const int wm = (warp >> 2) * 64;
    const int wn = (warp & 3) * 32;
    const int g = lane >> 2;
    const int t = lane & 3;
    const int cRow = blockIdx.y, cCol = blockIdx.x;

    const int aRow = tid >> 3;         // 0..31
    const int aCol = (tid & 7) * 4;    // 0..28
    const int bRow = tid >> 5;         // 0..7
    const int bCol = (tid & 31) * 4;   // 0..124

    const float* Ag = A + (size_t)(cRow * 128) * K;
    const float* Bg = B + cCol * 128;

    float acc[4][4][4];
    #pragma unroll
    for (int i = 0; i < 4; i++)
        #pragma unroll
        for (int j = 0; j < 4; j++)
            #pragma unroll
            for (int e = 0; e < 4; e++) acc[i][j][e] = 0.f;

    const int NT = K >> 5;   // K/32 tiles

    // ---- issue stage-0 loads ----
    {
        float* As = sm;
        float* Bs = sm + 128 * AS_STRIDE;
        #pragma unroll
        for (int r = 0; r < 4; r++)
            cp_async16(&As[(aRow + r * 32) * AS_STRIDE + aCol],
                       Ag + (size_t)(aRow + r * 32) * K + aCol);
        #pragma unroll
        for (int r = 0; r < 4; r++)
            cp_async16(&Bs[(bRow + r * 8) * BS_STRIDE + bCol],
                       Bg + (size_t)(bRow + r * 8) * N + bCol);
        CP_COMMIT();
    }

    for (int it = 0; it < NT; it++) {
        if (it + 1 < NT) {
            const int k0 = (it + 1) << 5;
            float* As = sm + ((it + 1) & 1) * STAGE_FLOATS;
            float* Bs = As + 128 * AS_STRIDE;
            #pragma unroll
            for (int r = 0; r < 4; r++)
                cp_async16(&As[(aRow + r * 32) * AS_STRIDE + aCol],
                           Ag + (size_t)(aRow + r * 32) * K + k0 + aCol);
            #pragma unroll
            for (int r = 0; r < 4; r++)
                cp_async16(&Bs[(bRow + r * 8) * BS_STRIDE + bCol],
                           Bg + (size_t)(k0 + bRow + r * 8) * N + bCol);
            CP_COMMIT();
            CP_WAIT(1);      // stage `it` complete
        } else {
            CP_WAIT(0);
        }
        __syncthreads();

        const unsigned* Asu = (const unsigned*)(sm + (it & 1) * STAGE_FLOATS);
        const unsigned* Bsu = Asu + 128 * AS_STRIDE;

        #pragma unroll
        for (int k8 = 0; k8 < 4; k8++) {
            const int kb = k8 * 8;
            unsigned af[4][4], bf[4][2];
            #pragma unroll
            for (int tm = 0; tm < 4; tm++) {
                int r0 = (wm + tm * 16 + g) * AS_STRIDE;
                af[tm][0] = Asu[r0 + kb + t];
                af[tm][1] = Asu[r0 + 8 * AS_STRIDE + kb + t];
                af[tm][2] = Asu[r0 + kb + 4 + t];
                af[tm][3] = Asu[r0 + 8 * AS_STRIDE + kb + 4 + t];
            }
            #pragma unroll
            for (int tn = 0; tn < 4; tn++) {
                bf[tn][0] = Bsu[(kb + t) * BS_STRIDE + wn + tn * 8 + g];
                bf[tn][1] = Bsu[(kb + 4 + t) * BS_STRIDE + wn + tn * 8 + g];
            }
            #pragma unroll
            for (int tm = 0; tm < 4; tm++)
                #pragma unroll
                for (int tn = 0; tn < 4; tn++)
                    mma_tf32(acc[tm][tn], af[tm], bf[tn]);
        }
        __syncthreads();   // all reads of this stage done before overwrite
    }

    #pragma unroll
    for (int tm = 0; tm < 4; tm++) {
        #pragma unroll
        for (int tn = 0; tn < 4; tn++) {
            int row = cRow * 128 + wm + tm * 16 + g;
            int col = cCol * 128 + wn + tn * 8 + 2 * t;
            float2 bb = *(const float2*)(bias + col);
            float2 v0 = make_float2(acc[tm][tn][0] + bb.x, acc[tm][tn][1] + bb.y);
            float2 v1 = make_float2(acc[tm][tn][2] + bb.x, acc[tm][tn][3] + bb.y);
            if (relu) {
                v0.x = fmaxf(v0.x, 0.f); v0.y = fmaxf(v0.y, 0.f);
                v1.x = fmaxf(v1.x, 0.f); v1.y = fmaxf(v1.y, 0.f);
            }
            *(float2*)(C + (size_t)row * N + col) = v0;
            *(float2*)(C + (size_t)(row + 8) * N + col) = v1;
        }
    }
}

// ---------------------------------------------------------------------------
// Flash attention on tensor cores (tf32 mma.sync m16n8k8).
// Block = (batch, head, 128-row Q tile); 256 threads = 8 warps.
// K/V/P fed to mma as raw fp32 bits (HW tf32 truncation); Q converted rna once.
// ---------------------------------------------------------------------------
#define QS_STRIDE 68
#define KS_STRIDE 68
#define VS_STRIDE 72
#define ATTN_SMEM_BYTES (64 * KS_STRIDE * 4 + 64 * VS_STRIDE * 4 + 256)

__global__ __launch_bounds__(256, 2) void attn3(
    const float* __restrict__ Q, const float* __restrict__ K,
    const float* __restrict__ V, const int* __restrict__ mask,
    float* __restrict__ O)
{
    extern __shared__ char smc[];
    float*    Qstage = (float*)smc;
    unsigned* Ks     = (unsigned*)smc;
    unsigned* Vs     = (unsigned*)(smc + 64 * KS_STRIDE * 4);
    float*    maskf  = (float*)(smc + 64 * KS_STRIDE * 4 + 64 * VS_STRIDE * 4);

    const int qt = blockIdx.x, h = blockIdx.y, b = blockIdx.z;
    const int tid  = threadIdx.x;
    const int lane = tid & 31;
    const int warp = tid >> 5;
    const int g = lane >> 2;
    const int t = lane & 3;
    const size_t hoff = (size_t)h * DK;
    const size_t qrow0 = (size_t)b * SEQ + qt * 128;

    // ---- Stage Q (scaled), extract per-warp fragments (rna convert, once) ----
    #pragma unroll
    for (int it = 0; it < 8; it++) {
        int idx = tid + it * 256;
        int r = idx >> 4;
        int c4 = (idx & 15) << 2;
        float4 v = *(const float4*)(Q + (qrow0 + r) * DMODEL + hoff + c4);
        v.x *= 0.125f; v.y *= 0.125f; v.z *= 0.125f; v.w *= 0.125f;
        *(float4*)&Qstage[r * QS_STRIDE + c4] = v;
    }
    __syncthreads();

    unsigned qf[8][4];
    {
        const int r0 = warp * 16;
        #pragma unroll
        for (int kk = 0; kk < 8; kk++) {
            qf[kk][0] = cvt_tf32(Qstage[(r0 + g)     * QS_STRIDE + kk * 8 + t]);
            qf[kk][1] = cvt_tf32(Qstage[(r0 + 8 + g) * QS_STRIDE + kk * 8 + t]);
            qf[kk][2] = cvt_tf32(Qstage[(r0 + g)     * QS_STRIDE + kk * 8 + 4 + t]);
            qf[kk][3] = cvt_tf32(Qstage[(r0 + 8 + g) * QS_STRIDE + kk * 8 + 4 + t]);
        }
    }
    __syncthreads();

    float m0 = -INFINITY, m1 = -INFINITY, l0 = 0.f, l1 = 0.f;
    float oacc[8][4];
    #pragma unroll
    for (int j = 0; j < 8; j++)
        #pragma unroll
        for (int e = 0; e < 4; e++) oacc[j][e] = 0.f;

    for (int kt = 0; kt < 32; kt++) {
        const size_t kvbase = ((size_t)b * SEQ + kt * 64) * DMODEL + hoff;

        // ---- Load K, V tiles (raw bits; no convert) ----
        #pragma unroll
        for (int it = 0; it < 4; it++) {
            int idx = tid + it * 256;
            int r = idx >> 4;
            int c4 = (idx & 15) << 2;
            *(uint4*)&Ks[r * KS_STRIDE + c4] =
                *(const uint4*)(K + kvbase + (size_t)r * DMODEL + c4);
            *(uint4*)&Vs[r * VS_STRIDE + c4] =
                *(const uint4*)(V + kvbase + (size_t)r * DMODEL + c4);
        }
        if (tid < 64)
            maskf[tid] = (mask[(size_t)b * SEQ + kt * 64 + tid] == 0) ? -INFINITY : 0.f;
        __syncthreads();

        // ---- S = Q @ K^T ----
        float sacc[8][4];
        #pragma unroll
        for (int j = 0; j < 8; j++)
            #pragma unroll
            for (int e = 0; e < 4; e++) sacc[j][e] = 0.f;

        #pragma unroll
        for (int kk = 0; kk < 8; kk++) {
            #pragma unroll
            for (int nj = 0; nj < 8; nj++) {
                unsigned bf[2];
                bf[0] = Ks[(nj * 8 + g) * KS_STRIDE + kk * 8 + t];
                bf[1] = Ks[(nj * 8 + g) * KS_STRIDE + kk * 8 + 4 + t];
                mma_tf32(sacc[nj], qf[kk], bf);
            }
        }

        // ---- Mask ----
        #pragma unroll
        for (int nj = 0; nj < 8; nj++) {
            float mk0 = maskf[nj * 8 + 2 * t];
            float mk1 = maskf[nj * 8 + 2 * t + 1];
            sacc[nj][0] += mk0; sacc[nj][1] += mk1;
            sacc[nj][2] += mk0; sacc[nj][3] += mk1;
        }

        // ---- Online softmax (rows g and g+8) ----
        {
            float mx0 = -INFINITY, mx1 = -INFINITY;
            #pragma unroll
            for (int nj = 0; nj < 8; nj++) {
                mx0 = fmaxf(mx0, fmaxf(sacc[nj][0], sacc[nj][1]));
                mx1 = fmaxf(mx1, fmaxf(sacc[nj][2], sacc[nj][3]));
            }
            mx0 = fmaxf(mx0, __shfl_xor_sync(0xffffffffu, mx0, 1));
            mx0 = fmaxf(mx0, __shfl_xor_sync(0xffffffffu, mx0, 2));
            mx1 = fmaxf(mx1, __shfl_xor_sync(0xffffffffu, mx1, 1));
            mx1 = fmaxf(mx1, __shfl_xor_sync(0xffffffffu, mx1, 2));
            float mn0 = fmaxf(m0, mx0), mn1 = fmaxf(m1, mx1);
            float corr0 = __expf(m0 - mn0), corr1 = __expf(m1 - mn1);

            float rs0 = 0.f, rs1 = 0.f;
            #pragma unroll
            for (int nj = 0; nj < 8; nj++) {
                sacc[nj][0] = __expf(sacc[nj][0] - mn0);
                sacc[nj][1] = __expf(sacc[nj][1] - mn0);
                sacc[nj][2] = __expf(sacc[nj][2] - mn1);
                sacc[nj][3] = __expf(sacc[nj][3] - mn1);
                rs0 += sacc[nj][0] + sacc[nj][1];
                rs1 += sacc[nj][2] + sacc[nj][3];
            }
            rs0 += __shfl_xor_sync(0xffffffffu, rs0, 1);
            rs0 += __shfl_xor_sync(0xffffffffu, rs0, 2);
            rs1 += __shfl_xor_sync(0xffffffffu, rs1, 1);
            rs1 += __shfl_xor_sync(0xffffffffu, rs1, 2);
            l0 = l0 * corr0 + rs0;  m0 = mn0;
            l1 = l1 * corr1 + rs1;  m1 = mn1;
            #pragma unroll
            for (int j = 0; j < 8; j++) {
                oacc[j][0] *= corr0; oacc[j][1] *= corr0;
                oacc[j][2] *= corr1; oacc[j][3] *= corr1;
            }
        }

        // ---- O += P @ V : remap P accum->A-frag via shuffles ----
        {
            const int src_lo = (lane & ~3) | (t >> 1);
            const int src_hi = src_lo + 2;
            const bool odd = (t & 1);
            #pragma unroll
            for (int j = 0; j < 8; j++) {
                float c0a = __shfl_sync(0xffffffffu, sacc[j][0], src_lo);
                float c1a = __shfl_sync(0xffffffffu, sacc[j][1], src_lo);
                float c0b = __shfl_sync(0xffffffffu, sacc[j][0], src_hi);
                float c1b = __shfl_sync(0xffffffffu, sacc[j][1], src_hi);
                float c2a = __shfl_sync(0xffffffffu, sacc[j][2], src_lo);
                float c3a = __shfl_sync(0xffffffffu, sacc[j][3], src_lo);
                float c2b = __shfl_sync(0xffffffffu, sacc[j][2], src_hi);
                float c3b = __shfl_sync(0xffffffffu, sacc[j][3], src_hi);
                unsigned af[4];
                af[0] = __float_as_uint(odd ? c1a : c0a);
                af[1] = __float_as_uint(odd ? c3a : c2a);
                af[2] = __float_as_uint(odd ? c1b : c0b);
                af[3] = __float_as_uint(odd ? c3b : c2b);
                #pragma unroll
                for (int jj = 0; jj < 8; jj++) {
                    unsigned bf[2];
                    bf[0] = Vs[(j * 8 + t)     * VS_STRIDE + jj * 8 + g];
                    bf[1] = Vs[(j * 8 + t + 4) * VS_STRIDE + jj * 8 + g];
                    mma_tf32(oacc[jj], af, bf);
                }
            }
        }
        __syncthreads();
    }

    // ---- Output ----
    {
        const float inv0 = 1.f / l0, inv1 = 1.f / l1;
        const size_t r0 = qrow0 + warp * 16 + g;
        #pragma unroll
        for (int jj = 0; jj < 8; jj++) {
            int col = jj * 8 + 2 * t;
            *(float2*)(O + r0 * DMODEL + hoff + col) =
                make_float2(oacc[jj][0] * inv0, oacc[jj][1] * inv0);
            *(float2*)(O + (r0 + 8) * DMODEL + hoff + col) =
                make_float2(oacc[jj][2] * inv1, oacc[jj][3] * inv1);
        }
    }
}

// ---------------------------------------------------------------------------
// out[row] = LayerNorm(a[row] + b[row]) * gamma + beta, one block per row.
// ---------------------------------------------------------------------------
__global__ __launch_bounds__(256) void add_ln_kernel(
    const float* __restrict__ a, const float* __restrict__ bsrc,
    const float* __restrict__ g, const float* __restrict__ be,
    float* __restrict__ out)
{
    const int row = blockIdx.x;
    const int tid = threadIdx.x;
    const float* pa = a + (size_t)row * DMODEL;
    const float* pb = bsrc + (size_t)row * DMODEL;

    float v[4];
    float sum = 0.f, sq = 0.f;
    #pragma unroll
    for (int i = 0; i < 4; i++) {
        int c = tid + i * 256;
        float x = pa[c] + pb[c];
        v[i] = x;
        sum += x;
        sq += x * x;
    }
    #pragma unroll
    for (int o = 16; o > 0; o >>= 1) {
        sum += __shfl_xor_sync(0xffffffffu, sum, o);
        sq  += __shfl_xor_sync(0xffffffffu, sq,  o);
    }
    __shared__ float ssum[8], ssq[8];
    if ((tid & 31) == 0) { ssum[tid >> 5] = sum; ssq[tid >> 5] = sq; }
    __syncthreads();
    if (tid < 32) {
        float s2 = (tid < 8) ? ssum[tid] : 0.f;
        float q2 = (tid < 8) ? ssq[tid] : 0.f;
        #pragma unroll
        for (int o = 4; o > 0; o >>= 1) {
            s2 += __shfl_xor_sync(0xffffffffu, s2, o);
            q2 += __shfl_xor_sync(0xffffffffu, q2, o);
        }
        if (tid == 0) { ssum[0] = s2; ssq[0] = q2; }
    }
    __syncthreads();
    const float mu   = ssum[0] * (1.f / DMODEL);
    const float var  = ssq[0] * (1.f / DMODEL) - mu * mu;
    const float rstd = rsqrtf(var + 1e-5f);

    float* po = out + (size_t)row * DMODEL;
    #pragma unroll
    for (int i = 0; i < 4; i++) {
        int c = tid + i * 256;
        po[c] = (v[i] - mu) * rstd * g[c] + be[c];
    }
}

// ---------------------------------------------------------------------------
// Launch
// ---------------------------------------------------------------------------
extern "C" void kernel_launch(void* const* d_in, const int* in_sizes, int n_in,
                              void* d_out, int out_size)
{
    (void)in_sizes; (void)n_in; (void)out_size;
    const float* x    = (const float*)d_in[0];
    const int*   mask = (const int*)  d_in[1];
    const float* w_q  = (const float*)d_in[2];
    const float* b_q  = (const float*)d_in[3];
    const float* w_k  = (const float*)d_in[4];
    const float* b_k  = (const float*)d_in[5];
    const float* w_v  = (const float*)d_in[6];
    const float* b_v  = (const float*)d_in[7];
    const float* w_o  = (const float*)d_in[8];
    const float* b_o  = (const float*)d_in[9];
    const float* w1   = (const float*)d_in[10];
    const float* b1   = (const float*)d_in[11];
    const float* w2   = (const float*)d_in[12];
    const float* b2   = (const float*)d_in[13];
    const float* g1   = (const float*)d_in[14];
    const float* be1  = (const float*)d_in[15];
    const float* g2   = (const float*)d_in[16];
    const float* be2  = (const float*)d_in[17];

    float *q, *k, *v, *ctx, *t1, *h, *ff;
    cudaGetSymbolAddress((void**)&q,   g_q);
    cudaGetSymbolAddress((void**)&k,   g_k);
    cudaGetSymbolAddress((void**)&v,   g_v);
    cudaGetSymbolAddress((void**)&ctx, g_ctx);
    cudaGetSymbolAddress((void**)&t1,  g_t1);
    cudaGetSymbolAddress((void**)&h,   g_h);
    cudaGetSymbolAddress((void**)&ff,  g_ff);

    cudaFuncSetAttribute(gemm_tf32, cudaFuncAttributeMaxDynamicSharedMemorySize,
                         GEMM_SMEM_BYTES);
    cudaFuncSetAttribute(attn3, cudaFuncAttributeMaxDynamicSharedMemorySize,
                         ATTN_SMEM_BYTES);

    dim3 blk(256);
    dim3 gProj(DMODEL / 128, MROWS / 128);   // (8, 64)
    dim3 gFF1(DFF / 128, MROWS / 128);       // (32, 64)
    dim3 gAtt(SEQ / 128, NHEADS, BATCH);     // (16, 16, 4)

    gemm_tf32<<<gProj, blk, GEMM_SMEM_BYTES>>>(MROWS, DMODEL, DMODEL, x, w_q, b_q, q, 0);
    gemm_tf32<<<gProj, blk, GEMM_SMEM_BYTES>>>(MROWS, DMODEL, DMODEL, x, w_k, b_k, k, 0);
    gemm_tf32<<<gProj, blk, GEMM_SMEM_BYTES>>>(MROWS, DMODEL, DMODEL, x, w_v, b_v, v, 0);

    attn3<<<gAtt, blk, ATTN_SMEM_BYTES>>>(q, k, v, mask, ctx);

    gemm_tf32<<<gProj, blk, GEMM_SMEM_BYTES>>>(MROWS, DMODEL, DMODEL, ctx, w_o, b_o, t1, 0);
    add_ln_kernel<<<MROWS, 256>>>(x, t1, g1, be1, h);

    gemm_tf32<<<gFF1, blk, GEMM_SMEM_BYTES>>>(MROWS, DFF, DMODEL, h, w1, b1, ff, 1);
    gemm_tf32<<<gProj, blk, GEMM_SMEM_BYTES>>>(MROWS, DMODEL, DFF, ff, w2, b2, t1, 0);
    add_ln_kernel<<<MROWS, 256>>>(h, t1, g2, be2, (float*)d_out);
}

// round 7
// speedup vs baseline: 4.4125x; 1.0303x over previous
#include <cuda_runtime.h>
#include <math.h>

// ---------------------------------------------------------------------------
// Problem constants
// ---------------------------------------------------------------------------
#define BATCH 4
#define SEQ   2048
#define DMODEL 1024
#define NHEADS 16
#define DK    64
#define DFF   4096
#define MROWS (BATCH * SEQ)   // 8192

// ---------------------------------------------------------------------------
// Scratch (no cudaMalloc allowed)
// ---------------------------------------------------------------------------
__device__ float g_q  [MROWS * DMODEL];
__device__ float g_k  [MROWS * DMODEL];
__device__ float g_v  [MROWS * DMODEL];
__device__ float g_ctx[MROWS * DMODEL];
__device__ float g_t1 [MROWS * DMODEL];
__device__ float g_h  [MROWS * DMODEL];
__device__ float g_hr [MROWS * DMODEL];
__device__ float g_ff [MROWS * DFF];
__device__ float g_xr [MROWS * DMODEL];
__device__ float g_wqr[DMODEL * DMODEL];
__device__ float g_wkr[DMODEL * DMODEL];
__device__ float g_wvr[DMODEL * DMODEL];
__device__ float g_wor[DMODEL * DMODEL];
__device__ float g_w1r[DMODEL * DFF];
__device__ float g_w2r[DFF * DMODEL];

// ---------------------------------------------------------------------------
// Helpers
// ---------------------------------------------------------------------------
__device__ __forceinline__ unsigned cvt_tf32(float x) {
    unsigned r;
    asm("cvt.rna.tf32.f32 %0, %1;" : "=r"(r) : "f"(x));
    return r;
}
__device__ __forceinline__ float rnd_tf32(float x) {
    return __uint_as_float(cvt_tf32(x));
}

__device__ __forceinline__ void mma_tf32(float* c, const unsigned* a, const unsigned* b) {
    asm volatile(
        "mma.sync.aligned.m16n8k8.row.col.f32.tf32.tf32.f32 "
        "{%0,%1,%2,%3}, {%4,%5,%6,%7}, {%8,%9}, {%0,%1,%2,%3};"
        : "+f"(c[0]), "+f"(c[1]), "+f"(c[2]), "+f"(c[3])
        : "r"(a[0]), "r"(a[1]), "r"(a[2]), "r"(a[3]), "r"(b[0]), "r"(b[1]));
}

__device__ __forceinline__ void cp_async16(void* smem_dst, const void* gmem_src) {
    unsigned saddr = (unsigned)__cvta_generic_to_shared(smem_dst);
    asm volatile("cp.async.cg.shared.global [%0], [%1], 16;"
                 :: "r"(saddr), "l"(gmem_src));
}
#define CP_COMMIT() asm volatile("cp.async.commit_group;")
#define CP_WAIT(n)  asm volatile("cp.async.wait_group %0;" :: "n"(n))

// ---------------------------------------------------------------------------
// Elementwise tf32 (rna) rounding: dst[i] = round_tf32(src[i])
// ---------------------------------------------------------------------------
__global__ __launch_bounds__(256) void round_tf32_kernel(
    const float* __restrict__ src, float* __restrict__ dst, int n4)
{
    int i = blockIdx.x * 256 + threadIdx.x;
    if (i < n4) {
        float4 v = ((const float4*)src)[i];
        v.x = rnd_tf32(v.x); v.y = rnd_tf32(v.y);
        v.z = rnd_tf32(v.z); v.w = rnd_tf32(v.w);
        ((float4*)dst)[i] = v;
    }
}

// ---------------------------------------------------------------------------
// TF32 tensor-core GEMM, 2-stage cp.async pipeline.
// C[M,N] = A[M,K] @ B[K,N] + bias[N] (optional ReLU, optional tf32-round out)
// BM=256, BN=128, BK=32. 256 threads = 8 warps (4x2), warp tile 64x64.
// Inputs are assumed pre-rounded to tf32 (raw bits fed to mma).
// ---------------------------------------------------------------------------
#define AS_STRIDE 36
#define BS_STRIDE 132
#define STAGE_FLOATS (256 * AS_STRIDE + 32 * BS_STRIDE)
#define GEMM_SMEM_BYTES (2 * STAGE_FLOATS * 4)

__global__ __launch_bounds__(256, 1) void gemm_tf32(
    int M, int N, int K,
    const float* __restrict__ A, const float* __restrict__ B,
    const float* __restrict__ bias, float* __restrict__ C, int relu, int rnd)
{
    extern __shared__ float sm[];

    const int tid  = threadIdx.x;
    const int lane = tid & 31;
    const int warp = tid >> 5;
    const int wm = (warp >> 1) * 64;   // 0,64,128,192
    const int wn = (warp & 1) * 64;    // 0,64
    const int g = lane >> 2;
    const int t = lane & 3;
    const int cRow = blockIdx.y, cCol = blockIdx.x;

    const int aRow = tid >> 3;         // 0..31
    const int aCol = (tid & 7) * 4;    // 0..28
    const int bRow = tid >> 5;         // 0..7
    const int bCol = (tid & 31) * 4;   // 0..124

    const float* Ag = A + (size_t)(cRow * 256) * K;
    const float* Bg = B + cCol * 128;

    float acc[4][8][4];
    #pragma unroll
    for (int i = 0; i < 4; i++)
        #pragma unroll
        for (int j = 0; j < 8; j++)
            #pragma unroll
            for (int e = 0; e < 4; e++) acc[i][j][e] = 0.f;

    const int NT = K >> 5;

    {
        float* As = sm;
        float* Bs = sm + 256 * AS_STRIDE;
        #pragma unroll
        for (int r = 0; r < 8; r++)
            cp_async16(&As[(aRow + r * 32) * AS_STRIDE + aCol],
                       Ag + (size_t)(aRow + r * 32) * K + aCol);
        #pragma unroll
        for (int r = 0; r < 4; r++)
            cp_async16(&Bs[(bRow + r * 8) * BS_STRIDE + bCol],
                       Bg + (size_t)(bRow + r * 8) * N + bCol);
        CP_COMMIT();
    }

    for (int it = 0; it < NT; it++) {
        if (it + 1 < NT) {
            const int k0 = (it + 1) << 5;
            float* As = sm + ((it + 1) & 1) * STAGE_FLOATS;
            float* Bs = As + 256 * AS_STRIDE;
            #pragma unroll
            for (int r = 0; r < 8; r++)
                cp_async16(&As[(aRow + r * 32) * AS_STRIDE + aCol],
                           Ag + (size_t)(aRow + r * 32) * K + k0 + aCol);
            #pragma unroll
            for (int r = 0; r < 4; r++)
                cp_async16(&Bs[(bRow + r * 8) * BS_STRIDE + bCol],
                           Bg + (size_t)(k0 + bRow + r * 8) * N + bCol);
            CP_COMMIT();
            CP_WAIT(1);
        } else {
            CP_WAIT(0);
        }
        __syncthreads();

        const unsigned* Asu = (const unsigned*)(sm + (it & 1) * STAGE_FLOATS);
        const unsigned* Bsu = Asu + 256 * AS_STRIDE;

        #pragma unroll
        for (int k8 = 0; k8 < 4; k8++) {
            const int kb = k8 * 8;
            unsigned af[4][4], bf[8][2];
            #pragma unroll
            for (int tm = 0; tm < 4; tm++) {
                int r0 = (wm + tm * 16 + g) * AS_STRIDE;
                af[tm][0] = Asu[r0 + kb + t];
                af[tm][1] = Asu[r0 + 8 * AS_STRIDE + kb + t];
                af[tm][2] = Asu[r0 + kb + 4 + t];
                af[tm][3] = Asu[r0 + 8 * AS_STRIDE + kb + 4 + t];
            }
            #pragma unroll
            for (int tn = 0; tn < 8; tn++) {
                bf[tn][0] = Bsu[(kb + t) * BS_STRIDE + wn + tn * 8 + g];
                bf[tn][1] = Bsu[(kb + 4 + t) * BS_STRIDE + wn + tn * 8 + g];
            }
            #pragma unroll
            for (int tm = 0; tm < 4; tm++)
                #pragma unroll
                for (int tn = 0; tn < 8; tn++)
                    mma_tf32(acc[tm][tn], af[tm], bf[tn]);
        }
        __syncthreads();
    }

    #pragma unroll
    for (int tm = 0; tm < 4; tm++) {
        #pragma unroll
        for (int tn = 0; tn < 8; tn++) {
            int row = cRow * 256 + wm + tm * 16 + g;
            int col = cCol * 128 + wn + tn * 8 + 2 * t;
            float2 bb = *(const float2*)(bias + col);
            float2 v0 = make_float2(acc[tm][tn][0] + bb.x, acc[tm][tn][1] + bb.y);
            float2 v1 = make_float2(acc[tm][tn][2] + bb.x, acc[tm][tn][3] + bb.y);
            if (relu) {
                v0.x = fmaxf(v0.x, 0.f); v0.y = fmaxf(v0.y, 0.f);
                v1.x = fmaxf(v1.x, 0.f); v1.y = fmaxf(v1.y, 0.f);
            }
            if (rnd) {
                v0.x = rnd_tf32(v0.x); v0.y = rnd_tf32(v0.y);
                v1.x = rnd_tf32(v1.x); v1.y = rnd_tf32(v1.y);
            }
            *(float2*)(C + (size_t)row * N + col) = v0;
            *(float2*)(C + (size_t)(row + 8) * N + col) = v1;
        }
    }
}

// ---------------------------------------------------------------------------
// Flash attention on tensor cores (tf32 mma.sync m16n8k8).
// Inputs Q/K/V are already exact tf32 (rounded by producing GEMM epilogue),
// so raw-bit feeding == rna semantics. Output ctx is rounded to tf32.
// ---------------------------------------------------------------------------
#define QS_STRIDE 68
#define KS_STRIDE 68
#define VS_STRIDE 72
#define ATTN_SMEM_BYTES (64 * KS_STRIDE * 4 + 64 * VS_STRIDE * 4 + 256)

__global__ __launch_bounds__(256, 2) void attn3(
    const float* __restrict__ Q, const float* __restrict__ K,
    const float* __restrict__ V, const int* __restrict__ mask,
    float* __restrict__ O)
{
    extern __shared__ char smc[];
    float*    Qstage = (float*)smc;
    unsigned* Ks     = (unsigned*)smc;
    unsigned* Vs     = (unsigned*)(smc + 64 * KS_STRIDE * 4);
    float*    maskf  = (float*)(smc + 64 * KS_STRIDE * 4 + 64 * VS_STRIDE * 4);

    const int qt = blockIdx.x, h = blockIdx.y, b = blockIdx.z;
    const int tid  = threadIdx.x;
    const int lane = tid & 31;
    const int warp = tid >> 5;
    const int g = lane >> 2;
    const int t = lane & 3;
    const size_t hoff = (size_t)h * DK;
    const size_t qrow0 = (size_t)b * SEQ + qt * 128;

    #pragma unroll
    for (int it = 0; it < 8; it++) {
        int idx = tid + it * 256;
        int r = idx >> 4;
        int c4 = (idx & 15) << 2;
        float4 v = *(const float4*)(Q + (qrow0 + r) * DMODEL + hoff + c4);
        v.x *= 0.125f; v.y *= 0.125f; v.z *= 0.125f; v.w *= 0.125f;
        *(float4*)&Qstage[r * QS_STRIDE + c4] = v;
    }
    __syncthreads();

    unsigned qf[8][4];
    {
        const int r0 = warp * 16;
        #pragma unroll
        for (int kk = 0; kk < 8; kk++) {
            qf[kk][0] = cvt_tf32(Qstage[(r0 + g)     * QS_STRIDE + kk * 8 + t]);
            qf[kk][1] = cvt_tf32(Qstage[(r0 + 8 + g) * QS_STRIDE + kk * 8 + t]);
            qf[kk][2] = cvt_tf32(Qstage[(r0 + g)     * QS_STRIDE + kk * 8 + 4 + t]);
            qf[kk][3] = cvt_tf32(Qstage[(r0 + 8 + g) * QS_STRIDE + kk * 8 + 4 + t]);
        }
    }
    __syncthreads();

    float m0 = -INFINITY, m1 = -INFINITY, l0 = 0.f, l1 = 0.f;
    float oacc[8][4];
    #pragma unroll
    for (int j = 0; j < 8; j++)
        #pragma unroll
        for (int e = 0; e < 4; e++) oacc[j][e] = 0.f;

    for (int kt = 0; kt < 32; kt++) {
        const size_t kvbase = ((size_t)b * SEQ + kt * 64) * DMODEL + hoff;

        #pragma unroll
        for (int it = 0; it < 4; it++) {
            int idx = tid + it * 256;
            int r = idx >> 4;
            int c4 = (idx & 15) << 2;
            *(uint4*)&Ks[r * KS_STRIDE + c4] =
                *(const uint4*)(K + kvbase + (size_t)r * DMODEL + c4);
            *(uint4*)&Vs[r * VS_STRIDE + c4] =
                *(const uint4*)(V + kvbase + (size_t)r * DMODEL + c4);
        }
        if (tid < 64)
            maskf[tid] = (mask[(size_t)b * SEQ + kt * 64 + tid] == 0) ? -INFINITY : 0.f;
        __syncthreads();

        float sacc[8][4];
        #pragma unroll
        for (int j = 0; j < 8; j++)
            #pragma unroll
            for (int e = 0; e < 4; e++) sacc[j][e] = 0.f;

        #pragma unroll
        for (int kk = 0; kk < 8; kk++) {
            #pragma unroll
            for (int nj = 0; nj < 8; nj++) {
                unsigned bf[2];
                bf[0] = Ks[(nj * 8 + g) * KS_STRIDE + kk * 8 + t];
                bf[1] = Ks[(nj * 8 + g) * KS_STRIDE + kk * 8 + 4 + t];
                mma_tf32(sacc[nj], qf[kk], bf);
            }
        }

        #pragma unroll
        for (int nj = 0; nj < 8; nj++) {
            float mk0 = maskf[nj * 8 + 2 * t];
            float mk1 = maskf[nj * 8 + 2 * t + 1];
            sacc[nj][0] += mk0; sacc[nj][1] += mk1;
            sacc[nj][2] += mk0; sacc[nj][3] += mk1;
        }

        {
            float mx0 = -INFINITY, mx1 = -INFINITY;
            #pragma unroll
            for (int nj = 0; nj < 8; nj++) {
                mx0 = fmaxf(mx0, fmaxf(sacc[nj][0], sacc[nj][1]));
                mx1 = fmaxf(mx1, fmaxf(sacc[nj][2], sacc[nj][3]));
            }
            mx0 = fmaxf(mx0, __shfl_xor_sync(0xffffffffu, mx0, 1));
            mx0 = fmaxf(mx0, __shfl_xor_sync(0xffffffffu, mx0, 2));
            mx1 = fmaxf(mx1, __shfl_xor_sync(0xffffffffu, mx1, 1));
            mx1 = fmaxf(mx1, __shfl_xor_sync(0xffffffffu, mx1, 2));
            float mn0 = fmaxf(m0, mx0), mn1 = fmaxf(m1, mx1);
            float corr0 = __expf(m0 - mn0), corr1 = __expf(m1 - mn1);

            float rs0 = 0.f, rs1 = 0.f;
            #pragma unroll
            for (int nj = 0; nj < 8; nj++) {
                sacc[nj][0] = __expf(sacc[nj][0] - mn0);
                sacc[nj][1] = __expf(sacc[nj][1] - mn0);
                sacc[nj][2] = __expf(sacc[nj][2] - mn1);
                sacc[nj][3] = __expf(sacc[nj][3] - mn1);
                rs0 += sacc[nj][0] + sacc[nj][1];
                rs1 += sacc[nj][2] + sacc[nj][3];
            }
            rs0 += __shfl_xor_sync(0xffffffffu, rs0, 1);
            rs0 += __shfl_xor_sync(0xffffffffu, rs0, 2);
            rs1 += __shfl_xor_sync(0xffffffffu, rs1, 1);
            rs1 += __shfl_xor_sync(0xffffffffu, rs1, 2);
            l0 = l0 * corr0 + rs0;  m0 = mn0;
            l1 = l1 * corr1 + rs1;  m1 = mn1;
            #pragma unroll
            for (int j = 0; j < 8; j++) {
                oacc[j][0] *= corr0; oacc[j][1] *= corr0;
                oacc[j][2] *= corr1; oacc[j][3] *= corr1;
            }
        }

        {
            const int src_lo = (lane & ~3) | (t >> 1);
            const int src_hi = src_lo + 2;
            const bool odd = (t & 1);
            #pragma unroll
            for (int j = 0; j < 8; j++) {
                float c0a = __shfl_sync(0xffffffffu, sacc[j][0], src_lo);
                float c1a = __shfl_sync(0xffffffffu, sacc[j][1], src_lo);
                float c0b = __shfl_sync(0xffffffffu, sacc[j][0], src_hi);
                float c1b = __shfl_sync(0xffffffffu, sacc[j][1], src_hi);
                float c2a = __shfl_sync(0xffffffffu, sacc[j][2], src_lo);
                float c3a = __shfl_sync(0xffffffffu, sacc[j][3], src_lo);
                float c2b = __shfl_sync(0xffffffffu, sacc[j][2], src_hi);
                float c3b = __shfl_sync(0xffffffffu, sacc[j][3], src_hi);
                unsigned af[4];
                af[0] = __float_as_uint(odd ? c1a : c0a);
                af[1] = __float_as_uint(odd ? c3a : c2a);
                af[2] = __float_as_uint(odd ? c1b : c0b);
                af[3] = __float_as_uint(odd ? c3b : c2b);
                #pragma unroll
                for (int jj = 0; jj < 8; jj++) {
                    unsigned bf[2];
                    bf[0] = Vs[(j * 8 + t)     * VS_STRIDE + jj * 8 + g];
                    bf[1] = Vs[(j * 8 + t + 4) * VS_STRIDE + jj * 8 + g];
                    mma_tf32(oacc[jj], af, bf);
                }
            }
        }
        __syncthreads();
    }

    {
        const float inv0 = 1.f / l0, inv1 = 1.f / l1;
        const size_t r0 = qrow0 + warp * 16 + g;
        #pragma unroll
        for (int jj = 0; jj < 8; jj++) {
            int col = jj * 8 + 2 * t;
            *(float2*)(O + r0 * DMODEL + hoff + col) =
                make_float2(rnd_tf32(oacc[jj][0] * inv0), rnd_tf32(oacc[jj][1] * inv0));
            *(float2*)(O + (r0 + 8) * DMODEL + hoff + col) =
                make_float2(rnd_tf32(oacc[jj][2] * inv1), rnd_tf32(oacc[jj][3] * inv1));
        }
    }
}

// ---------------------------------------------------------------------------
// out[row] = LayerNorm(a[row] + b[row]) * gamma + beta.
// Optionally also writes a tf32-rounded copy (out_r) for downstream GEMMs.
// ---------------------------------------------------------------------------
__global__ __launch_bounds__(256) void add_ln_kernel(
    const float* __restrict__ a, const float* __restrict__ bsrc,
    const float* __restrict__ g, const float* __restrict__ be,
    float* __restrict__ out, float* __restrict__ out_r)
{
    const int row = blockIdx.x;
    const int tid = threadIdx.x;
    const float* pa = a + (size_t)row * DMODEL;
    const float* pb = bsrc + (size_t)row * DMODEL;

    float v[4];
    float sum = 0.f, sq = 0.f;
    #pragma unroll
    for (int i = 0; i < 4; i++) {
        int c = tid + i * 256;
        float x = pa[c] + pb[c];
        v[i] = x;
        sum += x;
        sq += x * x;
    }
    #pragma unroll
    for (int o = 16; o > 0; o >>= 1) {
        sum += __shfl_xor_sync(0xffffffffu, sum, o);
        sq  += __shfl_xor_sync(0xffffffffu, sq,  o);
    }
    __shared__ float ssum[8], ssq[8];
    if ((tid & 31) == 0) { ssum[tid >> 5] = sum; ssq[tid >> 5] = sq; }
    __syncthreads();
    if (tid < 32) {
        float s2 = (tid < 8) ? ssum[tid] : 0.f;
        float q2 = (tid < 8) ? ssq[tid] : 0.f;
        #pragma unroll
        for (int o = 4; o > 0; o >>= 1) {
            s2 += __shfl_xor_sync(0xffffffffu, s2, o);
            q2 += __shfl_xor_sync(0xffffffffu, q2, o);
        }
        if (tid == 0) { ssum[0] = s2; ssq[0] = q2; }
    }
    __syncthreads();
    const float mu   = ssum[0] * (1.f / DMODEL);
    const float var  = ssq[0] * (1.f / DMODEL) - mu * mu;
    const float rstd = rsqrtf(var + 1e-5f);

    float* po = out + (size_t)row * DMODEL;
    float* pr = out_r ? out_r + (size_t)row * DMODEL : nullptr;
    #pragma unroll
    for (int i = 0; i < 4; i++) {
        int c = tid + i * 256;
        float y = (v[i] - mu) * rstd * g[c] + be[c];
        po[c] = y;
        if (pr) pr[c] = rnd_tf32(y);
    }
}

// ---------------------------------------------------------------------------
// Launch
// ---------------------------------------------------------------------------
extern "C" void kernel_launch(void* const* d_in, const int* in_sizes, int n_in,
                              void* d_out, int out_size)
{
    (void)in_sizes; (void)n_in; (void)out_size;
    const float* x    = (const float*)d_in[0];
    const int*   mask = (const int*)  d_in[1];
    const float* w_q  = (const float*)d_in[2];
    const float* b_q  = (const float*)d_in[3];
    const float* w_k  = (const float*)d_in[4];
    const float* b_k  = (const float*)d_in[5];
    const float* w_v  = (const float*)d_in[6];
    const float* b_v  = (const float*)d_in[7];
    const float* w_o  = (const float*)d_in[8];
    const float* b_o  = (const float*)d_in[9];
    const float* w1   = (const float*)d_in[10];
    const float* b1   = (const float*)d_in[11];
    const float* w2   = (const float*)d_in[12];
    const float* b2   = (const float*)d_in[13];
    const float* g1   = (const float*)d_in[14];
    const float* be1  = (const float*)d_in[15];
    const float* g2   = (const float*)d_in[16];
    const float* be2  = (const float*)d_in[17];

    float *q, *k, *v, *ctx, *t1, *h, *hr, *ff;
    float *xr, *wqr, *wkr, *wvr, *wor, *w1r, *w2r;
    cudaGetSymbolAddress((void**)&q,   g_q);
    cudaGetSymbolAddress((void**)&k,   g_k);
    cudaGetSymbolAddress((void**)&v,   g_v);
    cudaGetSymbolAddress((void**)&ctx, g_ctx);
    cudaGetSymbolAddress((void**)&t1,  g_t1);
    cudaGetSymbolAddress((void**)&h,   g_h);
    cudaGetSymbolAddress((void**)&hr,  g_hr);
    cudaGetSymbolAddress((void**)&ff,  g_ff);
    cudaGetSymbolAddress((void**)&xr,  g_xr);
    cudaGetSymbolAddress((void**)&wqr, g_wqr);
    cudaGetSymbolAddress((void**)&wkr, g_wkr);
    cudaGetSymbolAddress((void**)&wvr, g_wvr);
    cudaGetSymbolAddress((void**)&wor, g_wor);
    cudaGetSymbolAddress((void**)&w1r, g_w1r);
    cudaGetSymbolAddress((void**)&w2r, g_w2r);

    cudaFuncSetAttribute(gemm_tf32, cudaFuncAttributeMaxDynamicSharedMemorySize,
                         GEMM_SMEM_BYTES);
    cudaFuncSetAttribute(attn3, cudaFuncAttributeMaxDynamicSharedMemorySize,
                         ATTN_SMEM_BYTES);

    // ---- pre-round GEMM inputs to tf32 (rna) ----
    {
        const int TB = 256;
        int n;
        n = MROWS * DMODEL / 4;  round_tf32_kernel<<<(n + TB - 1) / TB, TB>>>(x,   xr,  n);
        n = DMODEL * DMODEL / 4; round_tf32_kernel<<<(n + TB - 1) / TB, TB>>>(w_q, wqr, n);
        n = DMODEL * DMODEL / 4; round_tf32_kernel<<<(n + TB - 1) / TB, TB>>>(w_k, wkr, n);
        n = DMODEL * DMODEL / 4; round_tf32_kernel<<<(n + TB - 1) / TB, TB>>>(w_v, wvr, n);
        n = DMODEL * DMODEL / 4; round_tf32_kernel<<<(n + TB - 1) / TB, TB>>>(w_o, wor, n);
        n = DMODEL * DFF / 4;    round_tf32_kernel<<<(n + TB - 1) / TB, TB>>>(w1,  w1r, n);
        n = DFF * DMODEL / 4;    round_tf32_kernel<<<(n + TB - 1) / TB, TB>>>(w2,  w2r, n);
    }

    dim3 blk(256);
    dim3 gProj(DMODEL / 128, MROWS / 256);   // (8, 32)
    dim3 gFF1(DFF / 128, MROWS / 256);       // (32, 32)
    dim3 gAtt(SEQ / 128, NHEADS, BATCH);     // (16, 16, 4)

    // QKV projections: outputs rounded to tf32 (consumed by attn mma)
    gemm_tf32<<<gProj, blk, GEMM_SMEM_BYTES>>>(MROWS, DMODEL, DMODEL, xr, wqr, b_q, q, 0, 1);
    gemm_tf32<<<gProj, blk, GEMM_SMEM_BYTES>>>(MROWS, DMODEL, DMODEL, xr, wkr, b_k, k, 0, 1);
    gemm_tf32<<<gProj, blk, GEMM_SMEM_BYTES>>>(MROWS, DMODEL, DMODEL, xr, wvr, b_v, v, 0, 1);

    attn3<<<gAtt, blk, ATTN_SMEM_BYTES>>>(q, k, v, mask, ctx);  // ctx rounded

    gemm_tf32<<<gProj, blk, GEMM_SMEM_BYTES>>>(MROWS, DMODEL, DMODEL, ctx, wor, b_o, t1, 0, 0);
    add_ln_kernel<<<MROWS, 256>>>(x, t1, g1, be1, h, hr);

    gemm_tf32<<<gFF1, blk, GEMM_SMEM_BYTES>>>(MROWS, DFF, DMODEL, hr, w1r, b1, ff, 1, 1);
    gemm_tf32<<<gProj, blk, GEMM_SMEM_BYTES>>>(MROWS, DMODEL, DFF, ff, w2r, b2, t1, 0, 0);
    add_ln_kernel<<<MROWS, 256>>>(h, t1, g2, be2, (float*)d_out, nullptr);
}